// round 1
// baseline (speedup 1.0000x reference)
#include <cuda_runtime.h>
#include <cstddef>

#define NN 20000
#define FEAT 512
#define FF (FEAT*FEAT)
#define EE 320000
#define EPS 1e-5f

// ---------------- scratch (device globals; no allocation allowed) ----------------
__device__ float g_hd[2][NN*FEAT];
__device__ float g_hp[2][NN*FEAT];
__device__ float g_m[4][NN*FEAT];
__device__ float g_Wsum[FF];
__device__ float g_bsum[FEAT];
__device__ float g_stats[2][2*FEAT];      // [ntype][sum(512) | sumsq(512)]
__device__ int   g_cnt[4][NN];
__device__ int   g_off[4][NN+1];
__device__ int   g_cur[4][NN];
__device__ int   g_srcid[4][EE];

// ---------------- utility kernels ----------------
__global__ void k_zero_int(int* p, int n) {
    int i = blockIdx.x*blockDim.x + threadIdx.x;
    if (i < n) p[i] = 0;
}
__global__ void k_zero_float(float* p, int n) {
    int i = blockIdx.x*blockDim.x + threadIdx.x;
    if (i < n) p[i] = 0.f;
}

// count in-degree per relation-direction
__global__ void k_count(const int* __restrict__ a_src, const int* __restrict__ a_dst,
                        const int* __restrict__ i_src, const int* __restrict__ i_dst, int e) {
    int idx = blockIdx.x*blockDim.x + threadIdx.x;
    if (idx >= e) return;
    atomicAdd(&g_cnt[0][a_dst[idx]], 1);
    atomicAdd(&g_cnt[1][a_src[idx]], 1);
    atomicAdd(&g_cnt[2][i_dst[idx]], 1);
    atomicAdd(&g_cnt[3][i_src[idx]], 1);
}

// one block per relation: exclusive scan cnt -> off (and cur copy)
__global__ void k_scan() {
    int r = blockIdx.x;
    int t = threadIdx.x;                  // 1024 threads
    const int per = (NN + 1023) / 1024;   // 20
    __shared__ int part[1024];
    int base = t * per;
    int sum = 0;
    for (int i = 0; i < per; i++) {
        int idx = base + i;
        if (idx < NN) sum += g_cnt[r][idx];
    }
    part[t] = sum;
    __syncthreads();
    for (int d = 1; d < 1024; d <<= 1) {
        int v = 0;
        if (t >= d) v = part[t-d];
        __syncthreads();
        if (t >= d) part[t] += v;
        __syncthreads();
    }
    int run = (t == 0) ? 0 : part[t-1];
    for (int i = 0; i < per; i++) {
        int idx = base + i;
        if (idx < NN) {
            g_off[r][idx] = run;
            g_cur[r][idx] = run;
            run += g_cnt[r][idx];
        }
    }
    if (t == 1023) g_off[r][NN] = run;
}

__global__ void k_fill(const int* __restrict__ a_src, const int* __restrict__ a_dst,
                       const int* __restrict__ i_src, const int* __restrict__ i_dst, int e) {
    int idx = blockIdx.x*blockDim.x + threadIdx.x;
    if (idx >= e) return;
    int p;
    p = atomicAdd(&g_cur[0][a_dst[idx]], 1); g_srcid[0][p] = a_src[idx];
    p = atomicAdd(&g_cur[1][a_src[idx]], 1); g_srcid[1][p] = a_dst[idx];
    p = atomicAdd(&g_cur[2][i_dst[idx]], 1); g_srcid[2][p] = i_src[idx];
    p = atomicAdd(&g_cur[3][i_src[idx]], 1); g_srcid[3][p] = i_dst[idx];
}

// one block (128 threads) per destination node; each thread owns a float4 column slice
__global__ void k_aggregate(float* __restrict__ out, const float* __restrict__ hsrc, int rel) {
    int node = blockIdx.x;
    int t = threadIdx.x;  // 0..127
    int beg = g_off[rel][node];
    int end = g_off[rel][node+1];
    float ax = 0.f, ay = 0.f, az = 0.f, aw = 0.f;
    for (int j = beg; j < end; j++) {
        int s = g_srcid[rel][j];
        float4 v = __ldg((const float4*)(hsrc + (size_t)s*FEAT) + t);
        ax += v.x; ay += v.y; az += v.z; aw += v.w;
    }
    float inv = (end > beg) ? 1.f / (float)(end - beg) : 0.f;
    float4 o; o.x = ax*inv; o.y = ay*inv; o.z = az*inv; o.w = aw*inv;
    *((float4*)(out + (size_t)node*FEAT) + t) = o;
}

// Wsum = Ws[0]+Ws[2]+Ws[3]; bsum = b[0]+b[2]+b[3]
__global__ void k_combine(const float* __restrict__ Ws, const float* __restrict__ b) {
    int i = blockIdx.x*blockDim.x + threadIdx.x;
    if (i < FF) g_Wsum[i] = Ws[i] + Ws[2*FF + i] + Ws[3*FF + i];
    if (i < FEAT) g_bsum[i] = b[i] + b[2*FEAT + i] + b[3*FEAT + i];
}

// ---------------- SGEMM: C[M,512] = sum_s A_s[M,512] @ B_s[512,512] + bias ----------------
#define BM 128
#define BN 128
#define BK 16
#define TM 8
#define TN 8

template<int NSEG>
__global__ __launch_bounds__(256)
void k_gemm(const float* __restrict__ A0, const float* __restrict__ B0,
            const float* __restrict__ A1, const float* __restrict__ B1,
            const float* __restrict__ A2, const float* __restrict__ B2,
            const float* __restrict__ A3, const float* __restrict__ B3,
            const float* __restrict__ bias, float* __restrict__ C, int M)
{
    __shared__ float As[BK][BM];
    __shared__ float Bs[BK][BN];

    const int tid  = threadIdx.x;
    const int row0 = blockIdx.y * BM;
    const int col0 = blockIdx.x * BN;

    const float* Aseg[4] = {A0, A1, A2, A3};
    const float* Bseg[4] = {B0, B1, B2, B3};

    float acc[TM][TN];
    #pragma unroll
    for (int i = 0; i < TM; i++)
        #pragma unroll
        for (int j = 0; j < TN; j++) acc[i][j] = 0.f;

    const int ty = tid >> 4;   // 0..15
    const int tx = tid & 15;   // 0..15

    #pragma unroll
    for (int s = 0; s < NSEG; s++) {
        const float* A  = Aseg[s];
        const float* Bp = Bseg[s];
        for (int k0 = 0; k0 < FEAT; k0 += BK) {
            // load A tile (BM x BK), transposed into As[k][row]
            #pragma unroll
            for (int l = 0; l < 2; l++) {
                int idx = tid + l*256;           // 0..511
                int ar = idx >> 2;               // 0..127
                int kc = (idx & 3) * 4;          // 0,4,8,12
                int gr = row0 + ar;
                float4 v = (gr < M) ? *(const float4*)(A + (size_t)gr*FEAT + k0 + kc)
                                    : make_float4(0.f,0.f,0.f,0.f);
                As[kc+0][ar] = v.x; As[kc+1][ar] = v.y;
                As[kc+2][ar] = v.z; As[kc+3][ar] = v.w;
            }
            // load B tile (BK x BN)
            #pragma unroll
            for (int l = 0; l < 2; l++) {
                int idx = tid + l*256;
                int br = idx >> 5;               // 0..15
                int cc = (idx & 31) * 4;         // 0..124
                float4 v = *(const float4*)(Bp + (size_t)(k0 + br)*FEAT + col0 + cc);
                *(float4*)(&Bs[br][cc]) = v;
            }
            __syncthreads();
            #pragma unroll
            for (int k = 0; k < BK; k++) {
                float a[TM], b[TN];
                #pragma unroll
                for (int i = 0; i < TM; i++) a[i] = As[k][ty*TM + i];
                #pragma unroll
                for (int j = 0; j < TN; j++) b[j] = Bs[k][tx*TN + j];
                #pragma unroll
                for (int i = 0; i < TM; i++)
                    #pragma unroll
                    for (int j = 0; j < TN; j++)
                        acc[i][j] += a[i] * b[j];
            }
            __syncthreads();
        }
    }

    #pragma unroll
    for (int i = 0; i < TM; i++) {
        int gr = row0 + ty*TM + i;
        if (gr < M) {
            #pragma unroll
            for (int j = 0; j < TN; j += 4) {
                int gc = col0 + tx*TN + j;
                float4 o;
                o.x = acc[i][j+0] + bias[gc+0];
                o.y = acc[i][j+1] + bias[gc+1];
                o.z = acc[i][j+2] + bias[gc+2];
                o.w = acc[i][j+3] + bias[gc+3];
                *(float4*)(C + (size_t)gr*FEAT + gc) = o;
            }
        }
    }
}

// ---------------- BatchNorm ----------------
// thread t owns columns t and t+256; blocks stride rows; atomically fold into stats
__global__ void k_colstats(const float* __restrict__ X, float* __restrict__ stats, int M) {
    int c0 = threadIdx.x, c1 = threadIdx.x + 256;
    float s0 = 0.f, s1 = 0.f, q0 = 0.f, q1 = 0.f;
    for (int r = blockIdx.x; r < M; r += gridDim.x) {
        float x0 = X[(size_t)r*FEAT + c0];
        float x1 = X[(size_t)r*FEAT + c1];
        s0 += x0; q0 += x0*x0;
        s1 += x1; q1 += x1*x1;
    }
    atomicAdd(&stats[c0], s0);
    atomicAdd(&stats[c1], s1);
    atomicAdd(&stats[FEAT + c0], q0);
    atomicAdd(&stats[FEAT + c1], q1);
}

__global__ void k_bnrelu(float* __restrict__ X, const float* __restrict__ stats,
                         const float* __restrict__ gamma, const float* __restrict__ beta, int M) {
    int idx = blockIdx.x*blockDim.x + threadIdx.x;
    if (idx >= M*FEAT) return;
    int c = idx & (FEAT-1);
    float invM = 1.f / (float)M;
    float mean = stats[c] * invM;
    float var  = stats[FEAT + c] * invM - mean*mean;
    float x = X[idx];
    x = gamma[c] * (x - mean) * rsqrtf(var + EPS) + beta[c];
    X[idx] = x > 0.f ? x : 0.f;
}

// ---------------- host side ----------------
static void* sym(const void* s) { void* p = nullptr; cudaGetSymbolAddress(&p, s); return p; }

extern "C" void kernel_launch(void* const* d_in, const int* in_sizes, int n_in,
                              void* d_out, int out_size)
{
    const float* h_d  = (const float*)d_in[0];
    const float* h_p  = (const float*)d_in[1];
    const float* Ws1  = (const float*)d_in[2];
    const float* Wn1  = (const float*)d_in[3];
    const float* b1   = (const float*)d_in[4];
    const float* Ws2  = (const float*)d_in[5];
    const float* Wn2  = (const float*)d_in[6];
    const float* b2   = (const float*)d_in[7];
    const float* gam  = (const float*)d_in[8];
    const float* bet  = (const float*)d_in[9];
    const float* pWd  = (const float*)d_in[10];
    const float* pbd  = (const float*)d_in[11];
    const float* pWp  = (const float*)d_in[12];
    const float* pbp  = (const float*)d_in[13];
    const int*  a_src = (const int*)d_in[14];
    const int*  a_dst = (const int*)d_in[15];
    const int*  i_src = (const int*)d_in[16];
    const int*  i_dst = (const int*)d_in[17];
    float* out = (float*)d_out;
    const int e = in_sizes[14];

    float* hd0   = (float*)sym(g_hd);
    float* hd1   = hd0 + (size_t)NN*FEAT;
    float* hp0   = (float*)sym(g_hp);
    float* hp1   = hp0 + (size_t)NN*FEAT;
    float* m0    = (float*)sym(g_m);
    float* m1    = m0 + (size_t)NN*FEAT;
    float* m2    = m0 + 2*(size_t)NN*FEAT;
    float* m3    = m0 + 3*(size_t)NN*FEAT;
    float* Wsum  = (float*)sym(g_Wsum);
    float* bsum  = (float*)sym(g_bsum);
    float* stats = (float*)sym(g_stats);
    int*   cnt   = (int*)sym(g_cnt);

    // ---- CSR build (shared by both layers) ----
    k_zero_int<<<(4*NN + 255)/256, 256>>>(cnt, 4*NN);
    k_count<<<(e + 255)/256, 256>>>(a_src, a_dst, i_src, i_dst, e);
    k_scan<<<4, 1024>>>();
    k_fill<<<(e + 255)/256, 256>>>(a_src, a_dst, i_src, i_dst, e);

    dim3 ggrid(FEAT/BN, (NN + BM - 1)/BM);

    // ---- one hetero layer ----
    auto layer = [&](const float* in_d, const float* in_p,
                     const float* Ws, const float* Wn, const float* b,
                     float* od, float* op, int li)
    {
        k_aggregate<<<NN, 128>>>(m0, in_d, 0);
        k_aggregate<<<NN, 128>>>(m1, in_p, 1);
        k_aggregate<<<NN, 128>>>(m2, in_p, 2);
        k_aggregate<<<NN, 128>>>(m3, in_p, 3);
        k_combine<<<(FF + 255)/256, 256>>>(Ws, b);
        // disease: hd @ Ws[1] + m1 @ Wn[1] + b[1]
        k_gemm<2><<<ggrid, 256>>>(in_d, Ws + FF, m1, Wn + FF,
                                  nullptr, nullptr, nullptr, nullptr,
                                  b + FEAT, od, NN);
        // protein: hp @ (Ws0+Ws2+Ws3) + m0@Wn0 + m2@Wn2 + m3@Wn3 + (b0+b2+b3)
        k_gemm<4><<<ggrid, 256>>>(in_p, Wsum, m0, Wn,
                                  m2, Wn + 2*(size_t)FF, m3, Wn + 3*(size_t)FF,
                                  bsum, op, NN);
        // BN + ReLU
        k_zero_float<<<(4*FEAT + 255)/256, 256>>>(stats, 4*FEAT);
        k_colstats<<<256, 256>>>(od, stats, NN);
        k_colstats<<<256, 256>>>(op, stats + 2*FEAT, NN);
        int nb = (NN*FEAT + 255)/256;
        k_bnrelu<<<nb, 256>>>(od, stats,            gam + (li*2 + 0)*FEAT, bet + (li*2 + 0)*FEAT, NN);
        k_bnrelu<<<nb, 256>>>(op, stats + 2*FEAT,   gam + (li*2 + 1)*FEAT, bet + (li*2 + 1)*FEAT, NN);
    };

    layer(h_d, h_p, Ws1, Wn1, b1, hd0, hp0, 0);
    layer(hd0, hp0, Ws2, Wn2, b2, hd1, hp1, 1);

    // ---- projections into d_out: [out_d | out_p] ----
    k_gemm<1><<<ggrid, 256>>>(hd1, pWd, nullptr, nullptr, nullptr, nullptr, nullptr, nullptr,
                              pbd, out, NN);
    k_gemm<1><<<ggrid, 256>>>(hp1, pWp, nullptr, nullptr, nullptr, nullptr, nullptr, nullptr,
                              pbp, out + (size_t)NN*FEAT, NN);
}

// round 2
// speedup vs baseline: 1.9719x; 1.9719x over previous
#include <cuda_runtime.h>
#include <cuda_bf16.h>
#include <cstdint>
#include <cstddef>

#define NN 20000
#define FEAT 512
#define FF (FEAT*FEAT)
#define EE 320000
#define EPS 1e-5f
#define GY ((NN + 127) / 128)

// ---------------- scratch (device globals; no allocation allowed) ----------------
__device__ float g_x[2][NN*FEAT];                 // fp32 layer outputs (0=disease,1=protein)
__device__ __nv_bfloat16 g_nbf[2][(size_t)NN*1024];       // node feats split: [row][hi512|lo512]
__device__ __nv_bfloat16 g_mbf[4][(size_t)NN*1024];       // aggregate means split
__device__ __nv_bfloat16 g_wbf[14][(size_t)2*FF];         // weights split: [hi FF | lo FF]
__device__ float g_bsum[2][FEAT];
__device__ float g_stats[4*FEAT];                 // [type0: sum|sumsq][type1: sum|sumsq]
__device__ int   g_cnt[4][NN];
__device__ int   g_off[4][NN+1];
__device__ int   g_cur[4][NN];
__device__ int   g_srcid[4][EE];

// ---------------- small utils ----------------
__global__ void k_zero_int(int* p, int n) {
    int i = blockIdx.x*blockDim.x + threadIdx.x;
    if (i < n) p[i] = 0;
}
__global__ void k_zero_float(float* p, int n) {
    int i = blockIdx.x*blockDim.x + threadIdx.x;
    if (i < n) p[i] = 0.f;
}

__device__ __forceinline__ void bsplit(float x, __nv_bfloat16& h, __nv_bfloat16& l) {
    h = __float2bfloat16(x);
    l = __float2bfloat16(x - __bfloat162float(h));
}

// ---------------- CSR build ----------------
__global__ void k_count(const int* __restrict__ a_src, const int* __restrict__ a_dst,
                        const int* __restrict__ i_src, const int* __restrict__ i_dst, int e) {
    int idx = blockIdx.x*blockDim.x + threadIdx.x;
    if (idx >= e) return;
    atomicAdd(&g_cnt[0][a_dst[idx]], 1);
    atomicAdd(&g_cnt[1][a_src[idx]], 1);
    atomicAdd(&g_cnt[2][i_dst[idx]], 1);
    atomicAdd(&g_cnt[3][i_src[idx]], 1);
}

__global__ void k_scan() {
    int r = blockIdx.x;
    int t = threadIdx.x;                  // 1024 threads
    const int per = (NN + 1023) / 1024;
    __shared__ int part[1024];
    int base = t * per;
    int sum = 0;
    for (int i = 0; i < per; i++) { int idx = base + i; if (idx < NN) sum += g_cnt[r][idx]; }
    part[t] = sum;
    __syncthreads();
    for (int d = 1; d < 1024; d <<= 1) {
        int v = 0;
        if (t >= d) v = part[t-d];
        __syncthreads();
        if (t >= d) part[t] += v;
        __syncthreads();
    }
    int run = (t == 0) ? 0 : part[t-1];
    for (int i = 0; i < per; i++) {
        int idx = base + i;
        if (idx < NN) { g_off[r][idx] = run; g_cur[r][idx] = run; run += g_cnt[r][idx]; }
    }
    if (t == 1023) g_off[r][NN] = run;
}

__global__ void k_fill(const int* __restrict__ a_src, const int* __restrict__ a_dst,
                       const int* __restrict__ i_src, const int* __restrict__ i_dst, int e) {
    int idx = blockIdx.x*blockDim.x + threadIdx.x;
    if (idx >= e) return;
    int p;
    p = atomicAdd(&g_cur[0][a_dst[idx]], 1); g_srcid[0][p] = a_src[idx];
    p = atomicAdd(&g_cur[1][a_src[idx]], 1); g_srcid[1][p] = a_dst[idx];
    p = atomicAdd(&g_cur[2][i_dst[idx]], 1); g_srcid[2][p] = i_src[idx];
    p = atomicAdd(&g_cur[3][i_src[idx]], 1); g_srcid[3][p] = i_dst[idx];
}

// ---------------- splits ----------------
// fp32 [M,512] -> bf16 [M, hi512|lo512]
__global__ void k_splitX(__nv_bfloat16* __restrict__ dst, const float* __restrict__ src, int M) {
    int i = blockIdx.x*blockDim.x + threadIdx.x;
    if (i >= M*128) return;
    int r = i >> 7, c = (i & 127) * 4;
    float4 v = *(const float4*)(src + (size_t)r*FEAT + c);
    float xv[4] = {v.x, v.y, v.z, v.w};
    __nv_bfloat16 h[4], l[4];
    #pragma unroll
    for (int j = 0; j < 4; j++) bsplit(xv[j], h[j], l[j]);
    size_t base = (size_t)r*1024 + c;
    __nv_bfloat162 t2;
    t2.x=h[0]; t2.y=h[1]; *(__nv_bfloat162*)(dst+base)     = t2;
    t2.x=h[2]; t2.y=h[3]; *(__nv_bfloat162*)(dst+base+2)   = t2;
    t2.x=l[0]; t2.y=l[1]; *(__nv_bfloat162*)(dst+base+512) = t2;
    t2.x=l[2]; t2.y=l[3]; *(__nv_bfloat162*)(dst+base+514) = t2;
}

__global__ void k_splitW(__nv_bfloat16* __restrict__ dst, const float* __restrict__ src) {
    int i = blockIdx.x*blockDim.x + threadIdx.x;
    if (i >= FF) return;
    __nv_bfloat16 h, l;
    bsplit(src[i], h, l);
    dst[i] = h; dst[FF + i] = l;
}

// Wsum = Ws[0]+Ws[2]+Ws[3] (split to dst); bsum = b[0]+b[2]+b[3]
__global__ void k_combineSplit(__nv_bfloat16* __restrict__ dst,
                               const float* __restrict__ Ws, const float* __restrict__ b,
                               float* __restrict__ bsum) {
    int i = blockIdx.x*blockDim.x + threadIdx.x;
    if (i < FF) {
        float x = Ws[i] + Ws[2*(size_t)FF + i] + Ws[3*(size_t)FF + i];
        __nv_bfloat16 h, l; bsplit(x, h, l);
        dst[i] = h; dst[FF + i] = l;
    }
    if (i < FEAT) bsum[i] = b[i] + b[2*FEAT + i] + b[3*FEAT + i];
}

// ---------------- aggregation (fp32 gather-mean -> split bf16) ----------------
__global__ void k_aggregate(__nv_bfloat16* __restrict__ outbf, const float* __restrict__ hsrc, int rel) {
    int node = blockIdx.x;
    int t = threadIdx.x;  // 0..127
    int beg = g_off[rel][node];
    int end = g_off[rel][node+1];
    float ax = 0.f, ay = 0.f, az = 0.f, aw = 0.f;
    for (int j = beg; j < end; j++) {
        int s = g_srcid[rel][j];
        float4 v = __ldg((const float4*)(hsrc + (size_t)s*FEAT) + t);
        ax += v.x; ay += v.y; az += v.z; aw += v.w;
    }
    float inv = (end > beg) ? 1.f / (float)(end - beg) : 0.f;
    float m[4] = {ax*inv, ay*inv, az*inv, aw*inv};
    __nv_bfloat16 h[4], l[4];
    #pragma unroll
    for (int j = 0; j < 4; j++) bsplit(m[j], h[j], l[j]);
    size_t base = (size_t)node*1024 + t*4;
    __nv_bfloat162 t2;
    t2.x=h[0]; t2.y=h[1]; *(__nv_bfloat162*)(outbf+base)     = t2;
    t2.x=h[2]; t2.y=h[3]; *(__nv_bfloat162*)(outbf+base+2)   = t2;
    t2.x=l[0]; t2.y=l[1]; *(__nv_bfloat162*)(outbf+base+512) = t2;
    t2.x=l[2]; t2.y=l[3]; *(__nv_bfloat162*)(outbf+base+514) = t2;
}

// ---------------- tensor-core GEMM ----------------
// C[M,512] = sum_s A_s[M,512](bf16, row stride 1024) @ B_s[512,512](bf16) + bias
struct Segs {
    const __nv_bfloat16* a[12];
    const __nv_bfloat16* b[12];
    int n;
};

__device__ __forceinline__ uint32_t sptr(const void* p) {
    return (uint32_t)__cvta_generic_to_shared(p);
}

__device__ __forceinline__ void cpa16(void* s, const void* g, bool pred) {
    uint32_t sa = sptr(s);
    int sz = pred ? 16 : 0;
    asm volatile("cp.async.cg.shared.global [%0], [%1], 16, %2;\n" :: "r"(sa), "l"(g), "r"(sz));
}

__global__ __launch_bounds__(256, 2)
void k_mma(const Segs segs, const float* __restrict__ bias, float* __restrict__ C, int M)
{
    __shared__ __align__(16) __nv_bfloat16 As[2][128][40];   // BK=32 + pad 8
    __shared__ __align__(16) __nv_bfloat16 Bs[2][32][136];   // BN=128 + pad 8

    const int tid  = threadIdx.x;
    const int lane = tid & 31;
    const int warp = tid >> 5;
    const int wm = (warp & 1) * 64;      // 2 warps along M, tile 64
    const int wn = (warp >> 1) * 32;     // 4 warps along N, tile 32
    const int row0 = blockIdx.y * 128;
    const int col0 = blockIdx.x * 128;

    float acc[4][4][4];
    #pragma unroll
    for (int i = 0; i < 4; i++)
        #pragma unroll
        for (int j = 0; j < 4; j++)
            #pragma unroll
            for (int k = 0; k < 4; k++) acc[i][j][k] = 0.f;

    const int T = segs.n * 16;  // K tiles of 32 per 512-K segment

    auto issue = [&](int t, int buf) {
        int s  = t >> 4;
        int k0 = (t & 15) * 32;
        const __nv_bfloat16* A = segs.a[s];
        const __nv_bfloat16* B = segs.b[s];
        int ar = tid >> 2;            // 0..63
        int ac = (tid & 3) * 8;       // 0,8,16,24
        #pragma unroll
        for (int h = 0; h < 2; h++) {
            int r = ar + h*64;
            int gr = row0 + r;
            cpa16(&As[buf][r][ac], A + (size_t)gr*1024 + k0 + ac, gr < M);
        }
        int br = tid >> 4;            // 0..15
        int bc = (tid & 15) * 8;      // 0..120
        #pragma unroll
        for (int h = 0; h < 2; h++) {
            int r = br + h*16;
            cpa16(&Bs[buf][r][bc], B + (size_t)(k0 + r)*512 + col0 + bc, true);
        }
        asm volatile("cp.async.commit_group;\n" ::: "memory");
    };

    issue(0, 0);

    for (int t = 0; t < T; t++) {
        int buf = t & 1;
        asm volatile("cp.async.wait_group 0;\n" ::: "memory");
        __syncthreads();
        if (t + 1 < T) issue(t + 1, buf ^ 1);

        const int g2 = lane >> 3, lr = lane & 7;
        #pragma unroll
        for (int ks = 0; ks < 2; ks++) {
            uint32_t af[4][4];
            #pragma unroll
            for (int mi = 0; mi < 4; mi++) {
                int arow = wm + mi*16 + (g2 & 1)*8 + lr;
                int acol = ks*16 + (g2 >> 1)*8;
                uint32_t ad = sptr(&As[buf][arow][acol]);
                asm volatile("ldmatrix.sync.aligned.m8n8.x4.shared.b16 {%0,%1,%2,%3}, [%4];\n"
                    : "=r"(af[mi][0]), "=r"(af[mi][1]), "=r"(af[mi][2]), "=r"(af[mi][3])
                    : "r"(ad));
            }
            uint32_t bfr[2][4];
            #pragma unroll
            for (int nj = 0; nj < 2; nj++) {
                int brow = ks*16 + (g2 & 1)*8 + lr;
                int bcol = wn + nj*16 + (g2 >> 1)*8;
                uint32_t bd = sptr(&Bs[buf][brow][bcol]);
                asm volatile("ldmatrix.sync.aligned.m8n8.x4.trans.shared.b16 {%0,%1,%2,%3}, [%4];\n"
                    : "=r"(bfr[nj][0]), "=r"(bfr[nj][1]), "=r"(bfr[nj][2]), "=r"(bfr[nj][3])
                    : "r"(bd));
            }
            #pragma unroll
            for (int mi = 0; mi < 4; mi++)
                #pragma unroll
                for (int ni = 0; ni < 4; ni++) {
                    uint32_t b0 = bfr[ni >> 1][(ni & 1)*2];
                    uint32_t b1 = bfr[ni >> 1][(ni & 1)*2 + 1];
                    asm volatile(
                        "mma.sync.aligned.m16n8k16.row.col.f32.bf16.bf16.f32 "
                        "{%0,%1,%2,%3}, {%4,%5,%6,%7}, {%8,%9}, {%0,%1,%2,%3};\n"
                        : "+f"(acc[mi][ni][0]), "+f"(acc[mi][ni][1]),
                          "+f"(acc[mi][ni][2]), "+f"(acc[mi][ni][3])
                        : "r"(af[mi][0]), "r"(af[mi][1]), "r"(af[mi][2]), "r"(af[mi][3]),
                          "r"(b0), "r"(b1));
                }
        }
    }

    // epilogue
    #pragma unroll
    for (int mi = 0; mi < 4; mi++) {
        int r0 = wm + mi*16 + (lane >> 2);
        #pragma unroll
        for (int ni = 0; ni < 4; ni++) {
            int gc = col0 + wn + ni*8 + (lane & 3)*2;
            float b0 = bias[gc], b1 = bias[gc+1];
            int gr0 = row0 + r0;
            if (gr0 < M) {
                float2 o; o.x = acc[mi][ni][0] + b0; o.y = acc[mi][ni][1] + b1;
                *(float2*)(C + (size_t)gr0*FEAT + gc) = o;
            }
            int gr1 = gr0 + 8;
            if (gr1 < M) {
                float2 o; o.x = acc[mi][ni][2] + b0; o.y = acc[mi][ni][3] + b1;
                *(float2*)(C + (size_t)gr1*FEAT + gc) = o;
            }
        }
    }
}

// ---------------- BatchNorm ----------------
__global__ void k_colstats(const float* __restrict__ X, float* __restrict__ stats, int M) {
    int c0 = threadIdx.x, c1 = threadIdx.x + 256;
    float s0 = 0.f, s1 = 0.f, q0 = 0.f, q1 = 0.f;
    for (int r = blockIdx.x; r < M; r += gridDim.x) {
        float x0 = X[(size_t)r*FEAT + c0];
        float x1 = X[(size_t)r*FEAT + c1];
        s0 += x0; q0 += x0*x0;
        s1 += x1; q1 += x1*x1;
    }
    atomicAdd(&stats[c0], s0);
    atomicAdd(&stats[c1], s1);
    atomicAdd(&stats[FEAT + c0], q0);
    atomicAdd(&stats[FEAT + c1], q1);
}

// BN+ReLU, writes fp32 (next layer aggregate source) and split bf16 (next GEMM A)
__global__ void k_bnrelu(float* __restrict__ X, __nv_bfloat16* __restrict__ Xbf,
                         const float* __restrict__ stats,
                         const float* __restrict__ gamma, const float* __restrict__ beta, int M) {
    int i = blockIdx.x*blockDim.x + threadIdx.x;
    if (i >= M*128) return;
    int r = i >> 7, c = (i & 127) * 4;
    float invM = 1.f / (float)M;
    float4 x = *(float4*)(X + (size_t)r*FEAT + c);
    float xv[4] = {x.x, x.y, x.z, x.w};
    float y[4];
    #pragma unroll
    for (int j = 0; j < 4; j++) {
        int cc = c + j;
        float mean = stats[cc] * invM;
        float var  = stats[FEAT + cc] * invM - mean*mean;
        float v = gamma[cc] * (xv[j] - mean) * rsqrtf(var + EPS) + beta[cc];
        y[j] = v > 0.f ? v : 0.f;
    }
    float4 o = {y[0], y[1], y[2], y[3]};
    *(float4*)(X + (size_t)r*FEAT + c) = o;
    __nv_bfloat16 h[4], l[4];
    #pragma unroll
    for (int j = 0; j < 4; j++) bsplit(y[j], h[j], l[j]);
    size_t base = (size_t)r*1024 + c;
    __nv_bfloat162 t2;
    t2.x=h[0]; t2.y=h[1]; *(__nv_bfloat162*)(Xbf+base)     = t2;
    t2.x=h[2]; t2.y=h[3]; *(__nv_bfloat162*)(Xbf+base+2)   = t2;
    t2.x=l[0]; t2.y=l[1]; *(__nv_bfloat162*)(Xbf+base+512) = t2;
    t2.x=l[2]; t2.y=l[3]; *(__nv_bfloat162*)(Xbf+base+514) = t2;
}

// ---------------- host ----------------
static void* sym(const void* s) { void* p = nullptr; cudaGetSymbolAddress(&p, s); return p; }

static void addTriple(Segs& s, const __nv_bfloat16* Abf, const __nv_bfloat16* Wbf) {
    s.a[s.n] = Abf;       s.b[s.n] = Wbf;      s.n++;   // hi*hi
    s.a[s.n] = Abf + 512; s.b[s.n] = Wbf;      s.n++;   // lo*hi
    s.a[s.n] = Abf;       s.b[s.n] = Wbf + FF; s.n++;   // hi*lo
}

extern "C" void kernel_launch(void* const* d_in, const int* in_sizes, int n_in,
                              void* d_out, int out_size)
{
    const float* h_d  = (const float*)d_in[0];
    const float* h_p  = (const float*)d_in[1];
    const float* Ws1  = (const float*)d_in[2];
    const float* Wn1  = (const float*)d_in[3];
    const float* b1   = (const float*)d_in[4];
    const float* Ws2  = (const float*)d_in[5];
    const float* Wn2  = (const float*)d_in[6];
    const float* b2   = (const float*)d_in[7];
    const float* gam  = (const float*)d_in[8];
    const float* bet  = (const float*)d_in[9];
    const float* pWd  = (const float*)d_in[10];
    const float* pbd  = (const float*)d_in[11];
    const float* pWp  = (const float*)d_in[12];
    const float* pbp  = (const float*)d_in[13];
    const int*  a_src = (const int*)d_in[14];
    const int*  a_dst = (const int*)d_in[15];
    const int*  i_src = (const int*)d_in[16];
    const int*  i_dst = (const int*)d_in[17];
    float* out = (float*)d_out;
    const int e = in_sizes[14];

    float* xd    = (float*)sym(g_x);
    float* xp    = xd + (size_t)NN*FEAT;
    __nv_bfloat16* nbf_d = (__nv_bfloat16*)sym(g_nbf);
    __nv_bfloat16* nbf_p = nbf_d + (size_t)NN*1024;
    __nv_bfloat16* mbf   = (__nv_bfloat16*)sym(g_mbf);
    __nv_bfloat16* mbf0  = mbf;
    __nv_bfloat16* mbf1  = mbf + 1*(size_t)NN*1024;
    __nv_bfloat16* mbf2  = mbf + 2*(size_t)NN*1024;
    __nv_bfloat16* mbf3  = mbf + 3*(size_t)NN*1024;
    __nv_bfloat16* wbf   = (__nv_bfloat16*)sym(g_wbf);
    auto W = [&](int slot) { return wbf + (size_t)slot * 2 * FF; };
    float* bsum0 = (float*)sym(g_bsum);
    float* bsum1 = bsum0 + FEAT;
    float* stats = (float*)sym(g_stats);
    int*   cnt   = (int*)sym(g_cnt);

    // ---- CSR build ----
    k_zero_int<<<(4*NN + 255)/256, 256>>>(cnt, 4*NN);
    k_count<<<(e + 255)/256, 256>>>(a_src, a_dst, i_src, i_dst, e);
    k_scan<<<4, 1024>>>();
    k_fill<<<(e + 255)/256, 256>>>(a_src, a_dst, i_src, i_dst, e);

    // ---- weight splits ----
    int wgrid = (FF + 255)/256;
    k_splitW<<<wgrid, 256>>>(W(0),  Ws1 + (size_t)FF);       // l1 disease self = Ws[1]
    k_splitW<<<wgrid, 256>>>(W(1),  Wn1 + (size_t)FF);       // l1 disease neigh = Wn[1]
    k_combineSplit<<<wgrid, 256>>>(W(2), Ws1, b1, bsum0);    // l1 protein self-sum
    k_splitW<<<wgrid, 256>>>(W(3),  Wn1);                    // Wn[0]
    k_splitW<<<wgrid, 256>>>(W(4),  Wn1 + 2*(size_t)FF);     // Wn[2]
    k_splitW<<<wgrid, 256>>>(W(5),  Wn1 + 3*(size_t)FF);     // Wn[3]
    k_splitW<<<wgrid, 256>>>(W(6),  Ws2 + (size_t)FF);
    k_splitW<<<wgrid, 256>>>(W(7),  Wn2 + (size_t)FF);
    k_combineSplit<<<wgrid, 256>>>(W(8), Ws2, b2, bsum1);
    k_splitW<<<wgrid, 256>>>(W(9),  Wn2);
    k_splitW<<<wgrid, 256>>>(W(10), Wn2 + 2*(size_t)FF);
    k_splitW<<<wgrid, 256>>>(W(11), Wn2 + 3*(size_t)FF);
    k_splitW<<<wgrid, 256>>>(W(12), pWd);
    k_splitW<<<wgrid, 256>>>(W(13), pWp);

    // ---- input splits ----
    int xgrid = (NN*128 + 255)/256;
    k_splitX<<<xgrid, 256>>>(nbf_d, h_d, NN);
    k_splitX<<<xgrid, 256>>>(nbf_p, h_p, NN);

    dim3 ggrid(4, GY);

    for (int l = 0; l < 2; l++) {
        const float* srcd = (l == 0) ? h_d : xd;
        const float* srcp = (l == 0) ? h_p : xp;
        const float* bl   = (l == 0) ? b1 : b2;
        float* bsum       = (l == 0) ? bsum0 : bsum1;
        int w0 = l * 6;

        // aggregates (read fp32 sources, write split bf16 means)
        k_aggregate<<<NN, 128>>>(mbf0, srcd, 0);
        k_aggregate<<<NN, 128>>>(mbf1, srcp, 1);
        k_aggregate<<<NN, 128>>>(mbf2, srcp, 2);
        k_aggregate<<<NN, 128>>>(mbf3, srcp, 3);

        // disease: hd @ Ws[1] + m1 @ Wn[1] + b[1]
        Segs sd; sd.n = 0;
        addTriple(sd, nbf_d, W(w0 + 0));
        addTriple(sd, mbf1,  W(w0 + 1));
        k_mma<<<ggrid, 256>>>(sd, bl + FEAT, xd, NN);

        // protein: hp @ Wsum + m0@Wn0 + m2@Wn2 + m3@Wn3 + bsum
        Segs sp; sp.n = 0;
        addTriple(sp, nbf_p, W(w0 + 2));
        addTriple(sp, mbf0,  W(w0 + 3));
        addTriple(sp, mbf2,  W(w0 + 4));
        addTriple(sp, mbf3,  W(w0 + 5));
        k_mma<<<ggrid, 256>>>(sp, bsum, xp, NN);

        // BN + ReLU (writes fp32 + split bf16)
        k_zero_float<<<(4*FEAT + 255)/256, 256>>>(stats, 4*FEAT);
        k_colstats<<<256, 256>>>(xd, stats, NN);
        k_colstats<<<256, 256>>>(xp, stats + 2*FEAT, NN);
        k_bnrelu<<<xgrid, 256>>>(xd, nbf_d, stats,          gam + (l*2 + 0)*FEAT, bet + (l*2 + 0)*FEAT, NN);
        k_bnrelu<<<xgrid, 256>>>(xp, nbf_p, stats + 2*FEAT, gam + (l*2 + 1)*FEAT, bet + (l*2 + 1)*FEAT, NN);
    }

    // ---- projections ----
    Segs s1; s1.n = 0; addTriple(s1, nbf_d, W(12));
    k_mma<<<ggrid, 256>>>(s1, pbd, out, NN);
    Segs s2; s2.n = 0; addTriple(s2, nbf_p, W(13));
    k_mma<<<ggrid, 256>>>(s2, pbp, out + (size_t)NN*FEAT, NN);
}

// round 3
// speedup vs baseline: 2.2833x; 1.1579x over previous
#include <cuda_runtime.h>
#include <cuda_bf16.h>
#include <cstdint>
#include <cstddef>

#define NN 20000
#define FEAT 512
#define FF (FEAT*FEAT)
#define EE 320000
#define EPS 1e-5f
#define GY ((NN + 127) / 128)

// ---------------- scratch (device globals; no allocation allowed) ----------------
__device__ float g_x[2][NN*FEAT];                 // fp32 layer outputs (0=disease,1=protein)
__device__ __nv_bfloat16 g_nbf[2][(size_t)NN*1024];       // node feats split: [row][hi512|lo512]
__device__ __nv_bfloat16 g_mbf[4][(size_t)NN*1024];       // aggregate means split
__device__ __nv_bfloat16 g_wbf[14][(size_t)2*FF];         // weights split: [hi FF | lo FF]
__device__ float g_bsum[2][FEAT];
__device__ float g_stats[4*FEAT];
__device__ int   g_cnt[4][NN];
__device__ int   g_off[4][NN+1];
__device__ int   g_cur[4][NN];
__device__ int   g_srcid[4][EE];

// ---------------- small utils ----------------
__global__ void k_zero_int(int* p, int n) {
    int i = blockIdx.x*blockDim.x + threadIdx.x;
    if (i < n) p[i] = 0;
}
__global__ void k_zero_float(float* p, int n) {
    int i = blockIdx.x*blockDim.x + threadIdx.x;
    if (i < n) p[i] = 0.f;
}

__device__ __forceinline__ void bsplit(float x, __nv_bfloat16& h, __nv_bfloat16& l) {
    h = __float2bfloat16(x);
    l = __float2bfloat16(x - __bfloat162float(h));
}

// ---------------- CSR build ----------------
__global__ void k_count(const int* __restrict__ a_src, const int* __restrict__ a_dst,
                        const int* __restrict__ i_src, const int* __restrict__ i_dst, int e) {
    int idx = blockIdx.x*blockDim.x + threadIdx.x;
    if (idx >= e) return;
    atomicAdd(&g_cnt[0][a_dst[idx]], 1);
    atomicAdd(&g_cnt[1][a_src[idx]], 1);
    atomicAdd(&g_cnt[2][i_dst[idx]], 1);
    atomicAdd(&g_cnt[3][i_src[idx]], 1);
}

__global__ void k_scan() {
    int r = blockIdx.x;
    int t = threadIdx.x;
    const int per = (NN + 1023) / 1024;
    __shared__ int part[1024];
    int base = t * per;
    int sum = 0;
    for (int i = 0; i < per; i++) { int idx = base + i; if (idx < NN) sum += g_cnt[r][idx]; }
    part[t] = sum;
    __syncthreads();
    for (int d = 1; d < 1024; d <<= 1) {
        int v = 0;
        if (t >= d) v = part[t-d];
        __syncthreads();
        if (t >= d) part[t] += v;
        __syncthreads();
    }
    int run = (t == 0) ? 0 : part[t-1];
    for (int i = 0; i < per; i++) {
        int idx = base + i;
        if (idx < NN) { g_off[r][idx] = run; g_cur[r][idx] = run; run += g_cnt[r][idx]; }
    }
    if (t == 1023) g_off[r][NN] = run;
}

__global__ void k_fill(const int* __restrict__ a_src, const int* __restrict__ a_dst,
                       const int* __restrict__ i_src, const int* __restrict__ i_dst, int e) {
    int idx = blockIdx.x*blockDim.x + threadIdx.x;
    if (idx >= e) return;
    int p;
    p = atomicAdd(&g_cur[0][a_dst[idx]], 1); g_srcid[0][p] = a_src[idx];
    p = atomicAdd(&g_cur[1][a_src[idx]], 1); g_srcid[1][p] = a_dst[idx];
    p = atomicAdd(&g_cur[2][i_dst[idx]], 1); g_srcid[2][p] = i_src[idx];
    p = atomicAdd(&g_cur[3][i_src[idx]], 1); g_srcid[3][p] = i_dst[idx];
}

// ---------------- splits ----------------
__global__ void k_splitX(__nv_bfloat16* __restrict__ dst, const float* __restrict__ src, int M) {
    int i = blockIdx.x*blockDim.x + threadIdx.x;
    if (i >= M*128) return;
    int r = i >> 7, c = (i & 127) * 4;
    float4 v = *(const float4*)(src + (size_t)r*FEAT + c);
    float xv[4] = {v.x, v.y, v.z, v.w};
    __nv_bfloat16 h[4], l[4];
    #pragma unroll
    for (int j = 0; j < 4; j++) bsplit(xv[j], h[j], l[j]);
    size_t base = (size_t)r*1024 + c;
    __nv_bfloat162 t2;
    t2.x=h[0]; t2.y=h[1]; *(__nv_bfloat162*)(dst+base)     = t2;
    t2.x=h[2]; t2.y=h[3]; *(__nv_bfloat162*)(dst+base+2)   = t2;
    t2.x=l[0]; t2.y=l[1]; *(__nv_bfloat162*)(dst+base+512) = t2;
    t2.x=l[2]; t2.y=l[3]; *(__nv_bfloat162*)(dst+base+514) = t2;
}

__global__ void k_splitW(__nv_bfloat16* __restrict__ dst, const float* __restrict__ src) {
    int i = blockIdx.x*blockDim.x + threadIdx.x;
    if (i >= FF) return;
    __nv_bfloat16 h, l;
    bsplit(src[i], h, l);
    dst[i] = h; dst[FF + i] = l;
}

__global__ void k_combineSplit(__nv_bfloat16* __restrict__ dst,
                               const float* __restrict__ Ws, const float* __restrict__ b,
                               float* __restrict__ bsum) {
    int i = blockIdx.x*blockDim.x + threadIdx.x;
    if (i < FF) {
        float x = Ws[i] + Ws[2*(size_t)FF + i] + Ws[3*(size_t)FF + i];
        __nv_bfloat16 h, l; bsplit(x, h, l);
        dst[i] = h; dst[FF + i] = l;
    }
    if (i < FEAT) bsum[i] = b[i] + b[2*FEAT + i] + b[3*FEAT + i];
}

// ---------------- aggregation ----------------
__global__ void k_aggregate(__nv_bfloat16* __restrict__ outbf, const float* __restrict__ hsrc, int rel) {
    int node = blockIdx.x;
    int t = threadIdx.x;  // 0..127
    int beg = g_off[rel][node];
    int end = g_off[rel][node+1];
    float ax = 0.f, ay = 0.f, az = 0.f, aw = 0.f;
    for (int j = beg; j < end; j++) {
        int s = g_srcid[rel][j];
        float4 v = __ldg((const float4*)(hsrc + (size_t)s*FEAT) + t);
        ax += v.x; ay += v.y; az += v.z; aw += v.w;
    }
    float inv = (end > beg) ? 1.f / (float)(end - beg) : 0.f;
    float m[4] = {ax*inv, ay*inv, az*inv, aw*inv};
    __nv_bfloat16 h[4], l[4];
    #pragma unroll
    for (int j = 0; j < 4; j++) bsplit(m[j], h[j], l[j]);
    size_t base = (size_t)node*1024 + t*4;
    __nv_bfloat162 t2;
    t2.x=h[0]; t2.y=h[1]; *(__nv_bfloat162*)(outbf+base)     = t2;
    t2.x=h[2]; t2.y=h[3]; *(__nv_bfloat162*)(outbf+base+2)   = t2;
    t2.x=l[0]; t2.y=l[1]; *(__nv_bfloat162*)(outbf+base+512) = t2;
    t2.x=l[2]; t2.y=l[3]; *(__nv_bfloat162*)(outbf+base+514) = t2;
}

// ---------------- tensor-core GEMM (merged split-triples) ----------------
// C[M,512] = sum_t { Ahi_t@Whi_t + Alo_t@Whi_t + Ahi_t@Wlo_t } + bias
// A rows have stride 1024 (hi at +0, lo at +512); W hi at +0, lo at +FF.
struct Trip {
    const __nv_bfloat16* a[4];
    const __nv_bfloat16* w[4];
    int n;
};

__device__ __forceinline__ uint32_t sptr(const void* p) {
    return (uint32_t)__cvta_generic_to_shared(p);
}
__device__ __forceinline__ void cpa16(uint32_t sa, const void* g, bool pred) {
    int sz = pred ? 16 : 0;
    asm volatile("cp.async.cg.shared.global [%0], [%1], 16, %2;\n" :: "r"(sa), "l"(g), "r"(sz));
}

#define APAD 40
#define BPAD 136
#define A_ELEMS (128*APAD)          // per buffer
#define B_ELEMS (32*BPAD)
// element offsets in dynamic smem
#define OFF_AH(buf) ((buf)*A_ELEMS)
#define OFF_AL(buf) (2*A_ELEMS + (buf)*A_ELEMS)
#define OFF_BH(buf) (4*A_ELEMS + (buf)*B_ELEMS)
#define OFF_BL(buf) (4*A_ELEMS + 2*B_ELEMS + (buf)*B_ELEMS)
#define SMEM_ELEMS (4*A_ELEMS + 4*B_ELEMS)
#define SMEM_BYTES (SMEM_ELEMS*2)

__global__ __launch_bounds__(256, 2)
void k_mma2(const Trip trip, const float* __restrict__ bias, float* __restrict__ C, int M)
{
    extern __shared__ __align__(16) __nv_bfloat16 sm[];

    const int tid  = threadIdx.x;
    const int lane = tid & 31;
    const int warp = tid >> 5;
    const int wm = (warp & 1) * 64;      // 2 warps along M (tile 64)
    const int wn = (warp >> 1) * 32;     // 4 warps along N (tile 32)
    const int row0 = blockIdx.y * 128;
    const int col0 = blockIdx.x * 128;

    float acc[4][4][4];
    #pragma unroll
    for (int i = 0; i < 4; i++)
        #pragma unroll
        for (int j = 0; j < 4; j++)
            #pragma unroll
            for (int k = 0; k < 4; k++) acc[i][j][k] = 0.f;

    const int T = trip.n * 16;   // 16 K-tiles of 32 per 512-K triple

    auto issue = [&](int t, int buf) {
        int s  = t >> 4;
        int k0 = (t & 15) * 32;
        const __nv_bfloat16* A = trip.a[s];
        const __nv_bfloat16* W = trip.w[s];
        int ar = tid >> 2;            // 0..63
        int ac = (tid & 3) * 8;       // 0,8,16,24
        #pragma unroll
        for (int h = 0; h < 2; h++) {
            int r = ar + h*64;
            int gr = row0 + r;
            bool p = gr < M;
            const __nv_bfloat16* gp = A + (size_t)gr*1024 + k0 + ac;
            cpa16(sptr(sm + OFF_AH(buf) + r*APAD + ac), gp, p);
            cpa16(sptr(sm + OFF_AL(buf) + r*APAD + ac), gp + 512, p);
        }
        int br = tid >> 4;            // 0..15
        int bc = (tid & 15) * 8;      // 0..120
        #pragma unroll
        for (int h = 0; h < 2; h++) {
            int r = br + h*16;
            const __nv_bfloat16* gp = W + (size_t)(k0 + r)*512 + col0 + bc;
            cpa16(sptr(sm + OFF_BH(buf) + r*BPAD + bc), gp, true);
            cpa16(sptr(sm + OFF_BL(buf) + r*BPAD + bc), gp + FF, true);
        }
        asm volatile("cp.async.commit_group;\n" ::: "memory");
    };

    issue(0, 0);

    const int g2 = lane >> 3, lr = lane & 7;

    for (int t = 0; t < T; t++) {
        int buf = t & 1;
        asm volatile("cp.async.wait_group 0;\n" ::: "memory");
        __syncthreads();
        if (t + 1 < T) issue(t + 1, buf ^ 1);

        #pragma unroll
        for (int ks = 0; ks < 2; ks++) {
            int arow = wm + (g2 & 1)*8 + lr;
            int acol = ks*16 + (g2 >> 1)*8;
            uint32_t ah[4][4], al[4][4];
            #pragma unroll
            for (int mi = 0; mi < 4; mi++) {
                uint32_t adh = sptr(sm + OFF_AH(buf) + (arow + mi*16)*APAD + acol);
                asm volatile("ldmatrix.sync.aligned.m8n8.x4.shared.b16 {%0,%1,%2,%3}, [%4];\n"
                    : "=r"(ah[mi][0]), "=r"(ah[mi][1]), "=r"(ah[mi][2]), "=r"(ah[mi][3])
                    : "r"(adh));
                uint32_t adl = sptr(sm + OFF_AL(buf) + (arow + mi*16)*APAD + acol);
                asm volatile("ldmatrix.sync.aligned.m8n8.x4.shared.b16 {%0,%1,%2,%3}, [%4];\n"
                    : "=r"(al[mi][0]), "=r"(al[mi][1]), "=r"(al[mi][2]), "=r"(al[mi][3])
                    : "r"(adl));
            }
            int brow = ks*16 + (g2 & 1)*8 + lr;
            uint32_t bh[2][4], bl[2][4];
            #pragma unroll
            for (int nj = 0; nj < 2; nj++) {
                int bcol = wn + nj*16 + (g2 >> 1)*8;
                uint32_t bdh = sptr(sm + OFF_BH(buf) + brow*BPAD + bcol);
                asm volatile("ldmatrix.sync.aligned.m8n8.x4.trans.shared.b16 {%0,%1,%2,%3}, [%4];\n"
                    : "=r"(bh[nj][0]), "=r"(bh[nj][1]), "=r"(bh[nj][2]), "=r"(bh[nj][3])
                    : "r"(bdh));
                uint32_t bdl = sptr(sm + OFF_BL(buf) + brow*BPAD + bcol);
                asm volatile("ldmatrix.sync.aligned.m8n8.x4.trans.shared.b16 {%0,%1,%2,%3}, [%4];\n"
                    : "=r"(bl[nj][0]), "=r"(bl[nj][1]), "=r"(bl[nj][2]), "=r"(bl[nj][3])
                    : "r"(bdl));
            }
            #pragma unroll
            for (int mi = 0; mi < 4; mi++)
                #pragma unroll
                for (int ni = 0; ni < 4; ni++) {
                    uint32_t b0h = bh[ni >> 1][(ni & 1)*2];
                    uint32_t b1h = bh[ni >> 1][(ni & 1)*2 + 1];
                    uint32_t b0l = bl[ni >> 1][(ni & 1)*2];
                    uint32_t b1l = bl[ni >> 1][(ni & 1)*2 + 1];
                    // hi*hi
                    asm volatile(
                        "mma.sync.aligned.m16n8k16.row.col.f32.bf16.bf16.f32 "
                        "{%0,%1,%2,%3}, {%4,%5,%6,%7}, {%8,%9}, {%0,%1,%2,%3};\n"
                        : "+f"(acc[mi][ni][0]), "+f"(acc[mi][ni][1]),
                          "+f"(acc[mi][ni][2]), "+f"(acc[mi][ni][3])
                        : "r"(ah[mi][0]), "r"(ah[mi][1]), "r"(ah[mi][2]), "r"(ah[mi][3]),
                          "r"(b0h), "r"(b1h));
                    // lo*hi
                    asm volatile(
                        "mma.sync.aligned.m16n8k16.row.col.f32.bf16.bf16.f32 "
                        "{%0,%1,%2,%3}, {%4,%5,%6,%7}, {%8,%9}, {%0,%1,%2,%3};\n"
                        : "+f"(acc[mi][ni][0]), "+f"(acc[mi][ni][1]),
                          "+f"(acc[mi][ni][2]), "+f"(acc[mi][ni][3])
                        : "r"(al[mi][0]), "r"(al[mi][1]), "r"(al[mi][2]), "r"(al[mi][3]),
                          "r"(b0h), "r"(b1h));
                    // hi*lo
                    asm volatile(
                        "mma.sync.aligned.m16n8k16.row.col.f32.bf16.bf16.f32 "
                        "{%0,%1,%2,%3}, {%4,%5,%6,%7}, {%8,%9}, {%0,%1,%2,%3};\n"
                        : "+f"(acc[mi][ni][0]), "+f"(acc[mi][ni][1]),
                          "+f"(acc[mi][ni][2]), "+f"(acc[mi][ni][3])
                        : "r"(ah[mi][0]), "r"(ah[mi][1]), "r"(ah[mi][2]), "r"(ah[mi][3]),
                          "r"(b0l), "r"(b1l));
                }
        }
    }

    // epilogue
    #pragma unroll
    for (int mi = 0; mi < 4; mi++) {
        int r0 = wm + mi*16 + (lane >> 2);
        #pragma unroll
        for (int ni = 0; ni < 4; ni++) {
            int gc = col0 + wn + ni*8 + (lane & 3)*2;
            float b0 = bias[gc], b1 = bias[gc+1];
            int gr0 = row0 + r0;
            if (gr0 < M) {
                float2 o; o.x = acc[mi][ni][0] + b0; o.y = acc[mi][ni][1] + b1;
                *(float2*)(C + (size_t)gr0*FEAT + gc) = o;
            }
            int gr1 = gr0 + 8;
            if (gr1 < M) {
                float2 o; o.x = acc[mi][ni][2] + b0; o.y = acc[mi][ni][3] + b1;
                *(float2*)(C + (size_t)gr1*FEAT + gc) = o;
            }
        }
    }
}

// ---------------- BatchNorm ----------------
__global__ void k_colstats(const float* __restrict__ X, float* __restrict__ stats, int M) {
    int c0 = threadIdx.x, c1 = threadIdx.x + 256;
    float s0 = 0.f, s1 = 0.f, q0 = 0.f, q1 = 0.f;
    for (int r = blockIdx.x; r < M; r += gridDim.x) {
        float x0 = X[(size_t)r*FEAT + c0];
        float x1 = X[(size_t)r*FEAT + c1];
        s0 += x0; q0 += x0*x0;
        s1 += x1; q1 += x1*x1;
    }
    atomicAdd(&stats[c0], s0);
    atomicAdd(&stats[c1], s1);
    atomicAdd(&stats[FEAT + c0], q0);
    atomicAdd(&stats[FEAT + c1], q1);
}

__global__ void k_bnrelu(float* __restrict__ X, __nv_bfloat16* __restrict__ Xbf,
                         const float* __restrict__ stats,
                         const float* __restrict__ gamma, const float* __restrict__ beta, int M) {
    int i = blockIdx.x*blockDim.x + threadIdx.x;
    if (i >= M*128) return;
    int r = i >> 7, c = (i & 127) * 4;
    float invM = 1.f / (float)M;
    float4 x = *(float4*)(X + (size_t)r*FEAT + c);
    float xv[4] = {x.x, x.y, x.z, x.w};
    float y[4];
    #pragma unroll
    for (int j = 0; j < 4; j++) {
        int cc = c + j;
        float mean = stats[cc] * invM;
        float var  = stats[FEAT + cc] * invM - mean*mean;
        float v = gamma[cc] * (xv[j] - mean) * rsqrtf(var + EPS) + beta[cc];
        y[j] = v > 0.f ? v : 0.f;
    }
    float4 o = {y[0], y[1], y[2], y[3]};
    *(float4*)(X + (size_t)r*FEAT + c) = o;
    __nv_bfloat16 h[4], l[4];
    #pragma unroll
    for (int j = 0; j < 4; j++) bsplit(y[j], h[j], l[j]);
    size_t base = (size_t)r*1024 + c;
    __nv_bfloat162 t2;
    t2.x=h[0]; t2.y=h[1]; *(__nv_bfloat162*)(Xbf+base)     = t2;
    t2.x=h[2]; t2.y=h[3]; *(__nv_bfloat162*)(Xbf+base+2)   = t2;
    t2.x=l[0]; t2.y=l[1]; *(__nv_bfloat162*)(Xbf+base+512) = t2;
    t2.x=l[2]; t2.y=l[3]; *(__nv_bfloat162*)(Xbf+base+514) = t2;
}

// ---------------- host ----------------
static void* sym(const void* s) { void* p = nullptr; cudaGetSymbolAddress(&p, s); return p; }

extern "C" void kernel_launch(void* const* d_in, const int* in_sizes, int n_in,
                              void* d_out, int out_size)
{
    const float* h_d  = (const float*)d_in[0];
    const float* h_p  = (const float*)d_in[1];
    const float* Ws1  = (const float*)d_in[2];
    const float* Wn1  = (const float*)d_in[3];
    const float* b1   = (const float*)d_in[4];
    const float* Ws2  = (const float*)d_in[5];
    const float* Wn2  = (const float*)d_in[6];
    const float* b2   = (const float*)d_in[7];
    const float* gam  = (const float*)d_in[8];
    const float* bet  = (const float*)d_in[9];
    const float* pWd  = (const float*)d_in[10];
    const float* pbd  = (const float*)d_in[11];
    const float* pWp  = (const float*)d_in[12];
    const float* pbp  = (const float*)d_in[13];
    const int*  a_src = (const int*)d_in[14];
    const int*  a_dst = (const int*)d_in[15];
    const int*  i_src = (const int*)d_in[16];
    const int*  i_dst = (const int*)d_in[17];
    float* out = (float*)d_out;
    const int e = in_sizes[14];

    float* xd    = (float*)sym(g_x);
    float* xp    = xd + (size_t)NN*FEAT;
    __nv_bfloat16* nbf_d = (__nv_bfloat16*)sym(g_nbf);
    __nv_bfloat16* nbf_p = nbf_d + (size_t)NN*1024;
    __nv_bfloat16* mbf   = (__nv_bfloat16*)sym(g_mbf);
    __nv_bfloat16* mbf0  = mbf;
    __nv_bfloat16* mbf1  = mbf + 1*(size_t)NN*1024;
    __nv_bfloat16* mbf2  = mbf + 2*(size_t)NN*1024;
    __nv_bfloat16* mbf3  = mbf + 3*(size_t)NN*1024;
    __nv_bfloat16* wbf   = (__nv_bfloat16*)sym(g_wbf);
    auto W = [&](int slot) { return wbf + (size_t)slot * 2 * FF; };
    float* bsum0 = (float*)sym(g_bsum);
    float* bsum1 = bsum0 + FEAT;
    float* stats = (float*)sym(g_stats);
    int*   cnt   = (int*)sym(g_cnt);

    cudaFuncSetAttribute(k_mma2, cudaFuncAttributeMaxDynamicSharedMemorySize, SMEM_BYTES);

    // ---- CSR build (launches 0-3) ----
    k_zero_int<<<(4*NN + 255)/256, 256>>>(cnt, 4*NN);
    k_count<<<(e + 255)/256, 256>>>(a_src, a_dst, i_src, i_dst, e);
    k_scan<<<4, 1024>>>();
    k_fill<<<(e + 255)/256, 256>>>(a_src, a_dst, i_src, i_dst, e);

    // ---- launch 4: input split (disease) ; launch 5: aggregate (ncu -s 5 captures this) ----
    int xgrid = (NN*128 + 255)/256;
    k_splitX<<<xgrid, 256>>>(nbf_d, h_d, NN);
    k_aggregate<<<NN, 128>>>(mbf1, h_p, 1);     // layer-1 rev_associates mean (profiled)
    k_splitX<<<xgrid, 256>>>(nbf_p, h_p, NN);

    // ---- weight splits ----
    int wgrid = (FF + 255)/256;
    k_splitW<<<wgrid, 256>>>(W(0),  Ws1 + (size_t)FF);
    k_splitW<<<wgrid, 256>>>(W(1),  Wn1 + (size_t)FF);
    k_combineSplit<<<wgrid, 256>>>(W(2), Ws1, b1, bsum0);
    k_splitW<<<wgrid, 256>>>(W(3),  Wn1);
    k_splitW<<<wgrid, 256>>>(W(4),  Wn1 + 2*(size_t)FF);
    k_splitW<<<wgrid, 256>>>(W(5),  Wn1 + 3*(size_t)FF);
    k_splitW<<<wgrid, 256>>>(W(6),  Ws2 + (size_t)FF);
    k_splitW<<<wgrid, 256>>>(W(7),  Wn2 + (size_t)FF);
    k_combineSplit<<<wgrid, 256>>>(W(8), Ws2, b2, bsum1);
    k_splitW<<<wgrid, 256>>>(W(9),  Wn2);
    k_splitW<<<wgrid, 256>>>(W(10), Wn2 + 2*(size_t)FF);
    k_splitW<<<wgrid, 256>>>(W(11), Wn2 + 3*(size_t)FF);
    k_splitW<<<wgrid, 256>>>(W(12), pWd);
    k_splitW<<<wgrid, 256>>>(W(13), pWp);

    dim3 ggrid(4, GY);

    for (int l = 0; l < 2; l++) {
        const float* srcd = (l == 0) ? h_d : xd;
        const float* srcp = (l == 0) ? h_p : xp;
        const float* bl   = (l == 0) ? b1 : b2;
        float* bsum       = (l == 0) ? bsum0 : bsum1;
        int w0 = l * 6;

        if (l > 0) k_aggregate<<<NN, 128>>>(mbf1, srcp, 1);   // layer-0 m1 was pre-launched
        k_aggregate<<<NN, 128>>>(mbf0, srcd, 0);
        k_aggregate<<<NN, 128>>>(mbf2, srcp, 2);
        k_aggregate<<<NN, 128>>>(mbf3, srcp, 3);

        // disease: hd@Ws[1] + m1@Wn[1] + b[1]
        Trip td; td.n = 2;
        td.a[0] = nbf_d; td.w[0] = W(w0 + 0);
        td.a[1] = mbf1;  td.w[1] = W(w0 + 1);
        k_mma2<<<ggrid, 256, SMEM_BYTES>>>(td, bl + FEAT, xd, NN);

        // protein: hp@Wsum + m0@Wn0 + m2@Wn2 + m3@Wn3 + bsum
        Trip tp; tp.n = 4;
        tp.a[0] = nbf_p; tp.w[0] = W(w0 + 2);
        tp.a[1] = mbf0;  tp.w[1] = W(w0 + 3);
        tp.a[2] = mbf2;  tp.w[2] = W(w0 + 4);
        tp.a[3] = mbf3;  tp.w[3] = W(w0 + 5);
        k_mma2<<<ggrid, 256, SMEM_BYTES>>>(tp, bsum, xp, NN);

        // BN + ReLU
        k_zero_float<<<(4*FEAT + 255)/256, 256>>>(stats, 4*FEAT);
        k_colstats<<<256, 256>>>(xd, stats, NN);
        k_colstats<<<256, 256>>>(xp, stats + 2*FEAT, NN);
        k_bnrelu<<<xgrid, 256>>>(xd, nbf_d, stats,          gam + (l*2 + 0)*FEAT, bet + (l*2 + 0)*FEAT, NN);
        k_bnrelu<<<xgrid, 256>>>(xp, nbf_p, stats + 2*FEAT, gam + (l*2 + 1)*FEAT, bet + (l*2 + 1)*FEAT, NN);
    }

    // ---- projections ----
    Trip t1; t1.n = 1; t1.a[0] = nbf_d; t1.w[0] = W(12);
    k_mma2<<<ggrid, 256, SMEM_BYTES>>>(t1, pbd, out, NN);
    Trip t2; t2.n = 1; t2.a[0] = nbf_p; t2.w[0] = W(13);
    k_mma2<<<ggrid, 256, SMEM_BYTES>>>(t2, pbp, out + (size_t)NN*FEAT, NN);
}

// round 5
// speedup vs baseline: 2.7896x; 1.2218x over previous
#include <cuda_runtime.h>
#include <cuda_bf16.h>
#include <cstdint>
#include <cstddef>

#define NN 20000
#define FEAT 512
#define FF (FEAT*FEAT)
#define EE 320000
#define EPS 1e-5f
#define GY ((NN + 127) / 128)

// ---------------- scratch (device globals; no allocation allowed) ----------------
__device__ float g_x[2][NN*FEAT];                       // fp32 layer outputs
__device__ __nv_bfloat16 g_nbf[2][(size_t)NN*1024];     // node feats split [row][hi512|lo512]
__device__ __nv_bfloat16 g_mbf[4][(size_t)NN*1024];     // aggregate means split
__device__ __nv_bfloat16 g_wbf[14][(size_t)2*FF];       // weights split: [hi FF | lo FF], W[k][n]
__device__ float g_bsum[2][FEAT];
__device__ float g_stats[8*FEAT];   // layer0: [sum_d|sq_d|sum_p|sq_p], layer1: +4*FEAT
__device__ int   g_cnt[4][NN];
__device__ int   g_off[4][NN+1];
__device__ int   g_cur[4][NN];
__device__ int   g_srcid[4][EE];

// ---------------- small utils ----------------
__global__ void k_zero_int(int* p, int n) {
    int i = blockIdx.x*blockDim.x + threadIdx.x;
    if (i < n) p[i] = 0;
}
__global__ void k_zero_float(float* p, int n) {
    int i = blockIdx.x*blockDim.x + threadIdx.x;
    if (i < n) p[i] = 0.f;
}
__device__ __forceinline__ void bsplit(float x, __nv_bfloat16& h, __nv_bfloat16& l) {
    h = __float2bfloat16(x);
    l = __float2bfloat16(x - __bfloat162float(h));
}

// ---------------- CSR build ----------------
__global__ void k_count(const int* __restrict__ a_src, const int* __restrict__ a_dst,
                        const int* __restrict__ i_src, const int* __restrict__ i_dst, int e) {
    int idx = blockIdx.x*blockDim.x + threadIdx.x;
    if (idx >= e) return;
    atomicAdd(&g_cnt[0][a_dst[idx]], 1);
    atomicAdd(&g_cnt[1][a_src[idx]], 1);
    atomicAdd(&g_cnt[2][i_dst[idx]], 1);
    atomicAdd(&g_cnt[3][i_src[idx]], 1);
}

__global__ void k_scan() {
    int r = blockIdx.x;
    int t = threadIdx.x;
    const int per = (NN + 1023) / 1024;
    __shared__ int part[1024];
    int base = t * per;
    int sum = 0;
    for (int i = 0; i < per; i++) { int idx = base + i; if (idx < NN) sum += g_cnt[r][idx]; }
    part[t] = sum;
    __syncthreads();
    for (int d = 1; d < 1024; d <<= 1) {
        int v = 0;
        if (t >= d) v = part[t-d];
        __syncthreads();
        if (t >= d) part[t] += v;
        __syncthreads();
    }
    int run = (t == 0) ? 0 : part[t-1];
    for (int i = 0; i < per; i++) {
        int idx = base + i;
        if (idx < NN) { g_off[r][idx] = run; g_cur[r][idx] = run; run += g_cnt[r][idx]; }
    }
    if (t == 1023) g_off[r][NN] = run;
}

__global__ void k_fill(const int* __restrict__ a_src, const int* __restrict__ a_dst,
                       const int* __restrict__ i_src, const int* __restrict__ i_dst, int e) {
    int idx = blockIdx.x*blockDim.x + threadIdx.x;
    if (idx >= e) return;
    int p;
    p = atomicAdd(&g_cur[0][a_dst[idx]], 1); g_srcid[0][p] = a_src[idx];
    p = atomicAdd(&g_cur[1][a_src[idx]], 1); g_srcid[1][p] = a_dst[idx];
    p = atomicAdd(&g_cur[2][i_dst[idx]], 1); g_srcid[2][p] = i_src[idx];
    p = atomicAdd(&g_cur[3][i_src[idx]], 1); g_srcid[3][p] = i_dst[idx];
}

// ---------------- splits ----------------
__global__ void k_splitX(__nv_bfloat16* __restrict__ dst, const float* __restrict__ src, int M) {
    int i = blockIdx.x*blockDim.x + threadIdx.x;
    if (i >= M*128) return;
    int r = i >> 7, c = (i & 127) * 4;
    float4 v = *(const float4*)(src + (size_t)r*FEAT + c);
    float xv[4] = {v.x, v.y, v.z, v.w};
    __nv_bfloat16 h[4], l[4];
    #pragma unroll
    for (int j = 0; j < 4; j++) bsplit(xv[j], h[j], l[j]);
    size_t base = (size_t)r*1024 + c;
    __nv_bfloat162 t2;
    t2.x=h[0]; t2.y=h[1]; *(__nv_bfloat162*)(dst+base)     = t2;
    t2.x=h[2]; t2.y=h[3]; *(__nv_bfloat162*)(dst+base+2)   = t2;
    t2.x=l[0]; t2.y=l[1]; *(__nv_bfloat162*)(dst+base+512) = t2;
    t2.x=l[2]; t2.y=l[3]; *(__nv_bfloat162*)(dst+base+514) = t2;
}

__global__ void k_splitW(__nv_bfloat16* __restrict__ dst, const float* __restrict__ src) {
    int i = blockIdx.x*blockDim.x + threadIdx.x;
    if (i >= FF) return;
    __nv_bfloat16 h, l;
    bsplit(src[i], h, l);
    dst[i] = h; dst[FF + i] = l;
}

__global__ void k_combineSplit(__nv_bfloat16* __restrict__ dst,
                               const float* __restrict__ Ws, const float* __restrict__ b,
                               float* __restrict__ bsum) {
    int i = blockIdx.x*blockDim.x + threadIdx.x;
    if (i < FF) {
        float x = Ws[i] + Ws[2*(size_t)FF + i] + Ws[3*(size_t)FF + i];
        __nv_bfloat16 h, l; bsplit(x, h, l);
        dst[i] = h; dst[FF + i] = l;
    }
    if (i < FEAT) bsum[i] = b[i] + b[2*FEAT + i] + b[3*FEAT + i];
}

// ---------------- aggregation ----------------
__global__ void k_aggregate(__nv_bfloat16* __restrict__ outbf, const float* __restrict__ hsrc, int rel) {
    int node = blockIdx.x;
    int t = threadIdx.x;  // 0..127
    int beg = g_off[rel][node];
    int end = g_off[rel][node+1];
    float ax = 0.f, ay = 0.f, az = 0.f, aw = 0.f;
    for (int j = beg; j < end; j++) {
        int s = g_srcid[rel][j];
        float4 v = __ldg((const float4*)(hsrc + (size_t)s*FEAT) + t);
        ax += v.x; ay += v.y; az += v.z; aw += v.w;
    }
    float inv = (end > beg) ? 1.f / (float)(end - beg) : 0.f;
    float m[4] = {ax*inv, ay*inv, az*inv, aw*inv};
    __nv_bfloat16 h[4], l[4];
    #pragma unroll
    for (int j = 0; j < 4; j++) bsplit(m[j], h[j], l[j]);
    size_t base = (size_t)node*1024 + t*4;
    __nv_bfloat162 t2;
    t2.x=h[0]; t2.y=h[1]; *(__nv_bfloat162*)(outbf+base)     = t2;
    t2.x=h[2]; t2.y=h[3]; *(__nv_bfloat162*)(outbf+base+2)   = t2;
    t2.x=l[0]; t2.y=l[1]; *(__nv_bfloat162*)(outbf+base+512) = t2;
    t2.x=l[2]; t2.y=l[3]; *(__nv_bfloat162*)(outbf+base+514) = t2;
}

// ---------------- tensor-core GEMM (merged split-triples + fused col-stats) ----------------
struct Trip {
    const __nv_bfloat16* a[4];
    const __nv_bfloat16* w[4];
    int n;
};

__device__ __forceinline__ uint32_t sptr(const void* p) {
    return (uint32_t)__cvta_generic_to_shared(p);
}
__device__ __forceinline__ void cpa16(uint32_t sa, const void* g, bool pred) {
    int sz = pred ? 16 : 0;
    asm volatile("cp.async.cg.shared.global [%0], [%1], 16, %2;\n" :: "r"(sa), "l"(g), "r"(sz));
}

#define APAD 40
#define BPAD 136
#define A_ELEMS (128*APAD)
#define B_ELEMS (32*BPAD)
#define OFF_AH(buf) ((buf)*A_ELEMS)
#define OFF_AL(buf) (2*A_ELEMS + (buf)*A_ELEMS)
#define OFF_BH(buf) (4*A_ELEMS + (buf)*B_ELEMS)
#define OFF_BL(buf) (4*A_ELEMS + 2*B_ELEMS + (buf)*B_ELEMS)
#define SMEM_ELEMS (4*A_ELEMS + 4*B_ELEMS)
#define SMEM_BYTES (SMEM_ELEMS*2)

__global__ __launch_bounds__(256, 2)
void k_mma2(const Trip trip, const float* __restrict__ bias, float* __restrict__ C,
            float* __restrict__ stats, int M)
{
    extern __shared__ __align__(16) __nv_bfloat16 sm[];

    const int tid  = threadIdx.x;
    const int lane = tid & 31;
    const int warp = tid >> 5;
    const int wm = (warp & 1) * 64;
    const int wn = (warp >> 1) * 32;
    const int row0 = blockIdx.y * 128;
    const int col0 = blockIdx.x * 128;

    float acc[4][4][4];
    #pragma unroll
    for (int i = 0; i < 4; i++)
        #pragma unroll
        for (int j = 0; j < 4; j++)
            #pragma unroll
            for (int k = 0; k < 4; k++) acc[i][j][k] = 0.f;

    const int T = trip.n * 16;

    auto issue = [&](int t, int buf) {
        int s  = t >> 4;
        int k0 = (t & 15) * 32;
        const __nv_bfloat16* A = trip.a[s];
        const __nv_bfloat16* W = trip.w[s];
        int ar = tid >> 2;
        int ac = (tid & 3) * 8;
        #pragma unroll
        for (int h = 0; h < 2; h++) {
            int r = ar + h*64;
            int gr = row0 + r;
            bool p = gr < M;
            const __nv_bfloat16* gp = A + (size_t)gr*1024 + k0 + ac;
            cpa16(sptr(sm + OFF_AH(buf) + r*APAD + ac), gp, p);
            cpa16(sptr(sm + OFF_AL(buf) + r*APAD + ac), gp + 512, p);
        }
        int br = tid >> 4;
        int bc = (tid & 15) * 8;
        #pragma unroll
        for (int h = 0; h < 2; h++) {
            int r = br + h*16;
            const __nv_bfloat16* gp = W + (size_t)(k0 + r)*512 + col0 + bc;
            cpa16(sptr(sm + OFF_BH(buf) + r*BPAD + bc), gp, true);
            cpa16(sptr(sm + OFF_BL(buf) + r*BPAD + bc), gp + FF, true);
        }
        asm volatile("cp.async.commit_group;\n" ::: "memory");
    };

    issue(0, 0);

    const int g2 = lane >> 3, lr = lane & 7;

    for (int t = 0; t < T; t++) {
        int buf = t & 1;
        asm volatile("cp.async.wait_group 0;\n" ::: "memory");
        __syncthreads();
        if (t + 1 < T) issue(t + 1, buf ^ 1);

        #pragma unroll
        for (int ks = 0; ks < 2; ks++) {
            int arow = wm + (g2 & 1)*8 + lr;
            int acol = ks*16 + (g2 >> 1)*8;
            uint32_t ah[4][4], al[4][4];
            #pragma unroll
            for (int mi = 0; mi < 4; mi++) {
                uint32_t adh = sptr(sm + OFF_AH(buf) + (arow + mi*16)*APAD + acol);
                asm volatile("ldmatrix.sync.aligned.m8n8.x4.shared.b16 {%0,%1,%2,%3}, [%4];\n"
                    : "=r"(ah[mi][0]), "=r"(ah[mi][1]), "=r"(ah[mi][2]), "=r"(ah[mi][3])
                    : "r"(adh));
                uint32_t adl = sptr(sm + OFF_AL(buf) + (arow + mi*16)*APAD + acol);
                asm volatile("ldmatrix.sync.aligned.m8n8.x4.shared.b16 {%0,%1,%2,%3}, [%4];\n"
                    : "=r"(al[mi][0]), "=r"(al[mi][1]), "=r"(al[mi][2]), "=r"(al[mi][3])
                    : "r"(adl));
            }
            int brow = ks*16 + (g2 & 1)*8 + lr;
            uint32_t bh[2][4], bl[2][4];
            #pragma unroll
            for (int nj = 0; nj < 2; nj++) {
                int bcol = wn + nj*16 + (g2 >> 1)*8;
                uint32_t bdh = sptr(sm + OFF_BH(buf) + brow*BPAD + bcol);
                asm volatile("ldmatrix.sync.aligned.m8n8.x4.trans.shared.b16 {%0,%1,%2,%3}, [%4];\n"
                    : "=r"(bh[nj][0]), "=r"(bh[nj][1]), "=r"(bh[nj][2]), "=r"(bh[nj][3])
                    : "r"(bdh));
                uint32_t bdl = sptr(sm + OFF_BL(buf) + brow*BPAD + bcol);
                asm volatile("ldmatrix.sync.aligned.m8n8.x4.trans.shared.b16 {%0,%1,%2,%3}, [%4];\n"
                    : "=r"(bl[nj][0]), "=r"(bl[nj][1]), "=r"(bl[nj][2]), "=r"(bl[nj][3])
                    : "r"(bdl));
            }
            #pragma unroll
            for (int mi = 0; mi < 4; mi++)
                #pragma unroll
                for (int ni = 0; ni < 4; ni++) {
                    uint32_t b0h = bh[ni >> 1][(ni & 1)*2];
                    uint32_t b1h = bh[ni >> 1][(ni & 1)*2 + 1];
                    uint32_t b0l = bl[ni >> 1][(ni & 1)*2];
                    uint32_t b1l = bl[ni >> 1][(ni & 1)*2 + 1];
                    asm volatile(
                        "mma.sync.aligned.m16n8k16.row.col.f32.bf16.bf16.f32 "
                        "{%0,%1,%2,%3}, {%4,%5,%6,%7}, {%8,%9}, {%0,%1,%2,%3};\n"
                        : "+f"(acc[mi][ni][0]), "+f"(acc[mi][ni][1]),
                          "+f"(acc[mi][ni][2]), "+f"(acc[mi][ni][3])
                        : "r"(ah[mi][0]), "r"(ah[mi][1]), "r"(ah[mi][2]), "r"(ah[mi][3]),
                          "r"(b0h), "r"(b1h));
                    asm volatile(
                        "mma.sync.aligned.m16n8k16.row.col.f32.bf16.bf16.f32 "
                        "{%0,%1,%2,%3}, {%4,%5,%6,%7}, {%8,%9}, {%0,%1,%2,%3};\n"
                        : "+f"(acc[mi][ni][0]), "+f"(acc[mi][ni][1]),
                          "+f"(acc[mi][ni][2]), "+f"(acc[mi][ni][3])
                        : "r"(al[mi][0]), "r"(al[mi][1]), "r"(al[mi][2]), "r"(al[mi][3]),
                          "r"(b0h), "r"(b1h));
                    asm volatile(
                        "mma.sync.aligned.m16n8k16.row.col.f32.bf16.bf16.f32 "
                        "{%0,%1,%2,%3}, {%4,%5,%6,%7}, {%8,%9}, {%0,%1,%2,%3};\n"
                        : "+f"(acc[mi][ni][0]), "+f"(acc[mi][ni][1]),
                          "+f"(acc[mi][ni][2]), "+f"(acc[mi][ni][3])
                        : "r"(ah[mi][0]), "r"(ah[mi][1]), "r"(ah[mi][2]), "r"(ah[mi][3]),
                          "r"(b0l), "r"(b1l));
                }
        }
    }

    // epilogue: store + fused column stats
    float vsum[4][2], vsq[4][2];
    #pragma unroll
    for (int ni = 0; ni < 4; ni++) { vsum[ni][0]=vsum[ni][1]=vsq[ni][0]=vsq[ni][1]=0.f; }

    #pragma unroll
    for (int mi = 0; mi < 4; mi++) {
        int gr0 = row0 + wm + mi*16 + (lane >> 2);
        int gr1 = gr0 + 8;
        bool p0 = gr0 < M, p1 = gr1 < M;
        #pragma unroll
        for (int ni = 0; ni < 4; ni++) {
            int gc = col0 + wn + ni*8 + (lane & 3)*2;
            float b0 = bias[gc], b1 = bias[gc+1];
            float v00 = acc[mi][ni][0] + b0, v01 = acc[mi][ni][1] + b1;
            float v10 = acc[mi][ni][2] + b0, v11 = acc[mi][ni][3] + b1;
            if (p0) {
                float2 o; o.x = v00; o.y = v01;
                *(float2*)(C + (size_t)gr0*FEAT + gc) = o;
                vsum[ni][0] += v00; vsq[ni][0] += v00*v00;
                vsum[ni][1] += v01; vsq[ni][1] += v01*v01;
            }
            if (p1) {
                float2 o; o.x = v10; o.y = v11;
                *(float2*)(C + (size_t)gr1*FEAT + gc) = o;
                vsum[ni][0] += v10; vsq[ni][0] += v10*v10;
                vsum[ni][1] += v11; vsq[ni][1] += v11*v11;
            }
        }
    }

    if (stats) {
        #pragma unroll
        for (int ni = 0; ni < 4; ni++) {
            #pragma unroll
            for (int j = 0; j < 2; j++) {
                float s = vsum[ni][j], q = vsq[ni][j];
                #pragma unroll
                for (int st = 4; st < 32; st <<= 1) {
                    s += __shfl_xor_sync(0xFFFFFFFFu, s, st);
                    q += __shfl_xor_sync(0xFFFFFFFFu, q, st);
                }
                if (lane < 4) {
                    int c = col0 + wn + ni*8 + lane*2 + j;
                    atomicAdd(&stats[c], s);
                    atomicAdd(&stats[FEAT + c], q);
                }
            }
        }
    }
}

// ---------------- BatchNorm (apply) ----------------
__global__ void k_bnrelu(float* __restrict__ X, __nv_bfloat16* __restrict__ Xbf,
                         const float* __restrict__ stats,
                         const float* __restrict__ gamma, const float* __restrict__ beta,
                         int M, int writeF32) {
    int i = blockIdx.x*blockDim.x + threadIdx.x;
    if (i >= M*128) return;
    int r = i >> 7, c = (i & 127) * 4;
    float invM = 1.f / (float)M;
    float4 x = *(float4*)(X + (size_t)r*FEAT + c);
    float xv[4] = {x.x, x.y, x.z, x.w};
    float y[4];
    #pragma unroll
    for (int j = 0; j < 4; j++) {
        int cc = c + j;
        float mean = stats[cc] * invM;
        float var  = stats[FEAT + cc] * invM - mean*mean;
        float v = gamma[cc] * (xv[j] - mean) * rsqrtf(var + EPS) + beta[cc];
        y[j] = v > 0.f ? v : 0.f;
    }
    if (writeF32) {
        float4 o = {y[0], y[1], y[2], y[3]};
        *(float4*)(X + (size_t)r*FEAT + c) = o;
    }
    __nv_bfloat16 h[4], l[4];
    #pragma unroll
    for (int j = 0; j < 4; j++) bsplit(y[j], h[j], l[j]);
    size_t base = (size_t)r*1024 + c;
    __nv_bfloat162 t2;
    t2.x=h[0]; t2.y=h[1]; *(__nv_bfloat162*)(Xbf+base)     = t2;
    t2.x=h[2]; t2.y=h[3]; *(__nv_bfloat162*)(Xbf+base+2)   = t2;
    t2.x=l[0]; t2.y=l[1]; *(__nv_bfloat162*)(Xbf+base+512) = t2;
    t2.x=l[2]; t2.y=l[3]; *(__nv_bfloat162*)(Xbf+base+514) = t2;
}

// ---------------- host ----------------
static void* sym(const void* s) { void* p = nullptr; cudaGetSymbolAddress(&p, s); return p; }

struct StreamCtx {
    cudaStream_t s1;
    cudaEvent_t ev[8];
    bool ok;
    StreamCtx() {
        ok = (cudaStreamCreateWithFlags(&s1, cudaStreamNonBlocking) == cudaSuccess);
        for (int i = 0; i < 8; i++)
            if (cudaEventCreateWithFlags(&ev[i], cudaEventDisableTiming) != cudaSuccess) ok = false;
    }
};

// event ids
enum { E_START=0, E_FILL, E_SPLITS, E_BND0, E_BNP0, E_M0, E_M1, E_S1 };

extern "C" void kernel_launch(void* const* d_in, const int* in_sizes, int n_in,
                              void* d_out, int out_size)
{
    static StreamCtx ctx;   // created on first (correctness) call, reused under capture

    const float* h_d  = (const float*)d_in[0];
    const float* h_p  = (const float*)d_in[1];
    const float* Ws1  = (const float*)d_in[2];
    const float* Wn1  = (const float*)d_in[3];
    const float* b1   = (const float*)d_in[4];
    const float* Ws2  = (const float*)d_in[5];
    const float* Wn2  = (const float*)d_in[6];
    const float* b2   = (const float*)d_in[7];
    const float* gam  = (const float*)d_in[8];
    const float* bet  = (const float*)d_in[9];
    const float* pWd  = (const float*)d_in[10];
    const float* pbd  = (const float*)d_in[11];
    const float* pWp  = (const float*)d_in[12];
    const float* pbp  = (const float*)d_in[13];
    const int*  a_src = (const int*)d_in[14];
    const int*  a_dst = (const int*)d_in[15];
    const int*  i_src = (const int*)d_in[16];
    const int*  i_dst = (const int*)d_in[17];
    float* out = (float*)d_out;
    const int e = in_sizes[14];

    float* xd    = (float*)sym(g_x);
    float* xp    = xd + (size_t)NN*FEAT;
    __nv_bfloat16* nbf_d = (__nv_bfloat16*)sym(g_nbf);
    __nv_bfloat16* nbf_p = nbf_d + (size_t)NN*1024;
    __nv_bfloat16* mbf   = (__nv_bfloat16*)sym(g_mbf);
    __nv_bfloat16* mbf0  = mbf;
    __nv_bfloat16* mbf1  = mbf + 1*(size_t)NN*1024;
    __nv_bfloat16* mbf2  = mbf + 2*(size_t)NN*1024;
    __nv_bfloat16* mbf3  = mbf + 3*(size_t)NN*1024;
    __nv_bfloat16* wbf   = (__nv_bfloat16*)sym(g_wbf);
    auto W = [&](int slot) { return wbf + (size_t)slot * 2 * FF; };
    float* bsum0 = (float*)sym(g_bsum);
    float* bsum1 = bsum0 + FEAT;
    float* st    = (float*)sym(g_stats);   // 8*FEAT
    float* st0d = st, *st0p = st + 2*FEAT, *st1d = st + 4*FEAT, *st1p = st + 6*FEAT;
    int*   cnt   = (int*)sym(g_cnt);

    cudaFuncSetAttribute(k_mma2, cudaFuncAttributeMaxDynamicSharedMemorySize, SMEM_BYTES);

    const bool ok = ctx.ok;
    cudaStream_t S0 = 0;
    cudaStream_t S1 = ok ? ctx.s1 : (cudaStream_t)0;
    auto rec  = [&](int i, cudaStream_t s) { if (ok) cudaEventRecord(ctx.ev[i], s); };
    auto wait = [&](cudaStream_t s, int i)  { if (ok) cudaStreamWaitEvent(s, ctx.ev[i], 0); };

    int xgrid = (NN*128 + 255)/256;
    int wgrid = (FF + 255)/256;
    dim3 ggrid(4, GY);

    // fork
    rec(E_START, S0);
    wait(S1, E_START);

    // ---- S0: CSR build ----
    k_zero_int<<<(4*NN + 255)/256, 256, 0, S0>>>(cnt, 4*NN);
    k_count<<<(e + 255)/256, 256, 0, S0>>>(a_src, a_dst, i_src, i_dst, e);
    k_scan<<<4, 1024, 0, S0>>>();
    k_fill<<<(e + 255)/256, 256, 0, S0>>>(a_src, a_dst, i_src, i_dst, e);
    rec(E_FILL, S0);
    k_aggregate<<<NN, 128, 0, S0>>>(mbf1, h_p, 1);              // layer0 m1

    // ---- S1: splits + zero stats ----
    k_splitX<<<xgrid, 256, 0, S1>>>(nbf_d, h_d, NN);
    k_splitX<<<xgrid, 256, 0, S1>>>(nbf_p, h_p, NN);
    k_splitW<<<wgrid, 256, 0, S1>>>(W(0),  Ws1 + (size_t)FF);
    k_splitW<<<wgrid, 256, 0, S1>>>(W(1),  Wn1 + (size_t)FF);
    k_combineSplit<<<wgrid, 256, 0, S1>>>(W(2), Ws1, b1, bsum0);
    k_splitW<<<wgrid, 256, 0, S1>>>(W(3),  Wn1);
    k_splitW<<<wgrid, 256, 0, S1>>>(W(4),  Wn1 + 2*(size_t)FF);
    k_splitW<<<wgrid, 256, 0, S1>>>(W(5),  Wn1 + 3*(size_t)FF);
    k_splitW<<<wgrid, 256, 0, S1>>>(W(6),  Ws2 + (size_t)FF);
    k_splitW<<<wgrid, 256, 0, S1>>>(W(7),  Wn2 + (size_t)FF);
    k_combineSplit<<<wgrid, 256, 0, S1>>>(W(8), Ws2, b2, bsum1);
    k_splitW<<<wgrid, 256, 0, S1>>>(W(9),  Wn2);
    k_splitW<<<wgrid, 256, 0, S1>>>(W(10), Wn2 + 2*(size_t)FF);
    k_splitW<<<wgrid, 256, 0, S1>>>(W(11), Wn2 + 3*(size_t)FF);
    k_splitW<<<wgrid, 256, 0, S1>>>(W(12), pWd);
    k_splitW<<<wgrid, 256, 0, S1>>>(W(13), pWp);
    k_zero_float<<<(8*FEAT + 255)/256, 256, 0, S1>>>(st, 8*FEAT);
    rec(E_SPLITS, S1);

    // ---- S1: layer0 protein chain ----
    wait(S1, E_FILL);
    k_aggregate<<<NN, 128, 0, S1>>>(mbf0, h_d, 0);
    k_aggregate<<<NN, 128, 0, S1>>>(mbf2, h_p, 2);
    k_aggregate<<<NN, 128, 0, S1>>>(mbf3, h_p, 3);
    Trip tp0; tp0.n = 4;
    tp0.a[0] = nbf_p; tp0.w[0] = W(2);
    tp0.a[1] = mbf0;  tp0.w[1] = W(3);
    tp0.a[2] = mbf2;  tp0.w[2] = W(4);
    tp0.a[3] = mbf3;  tp0.w[3] = W(5);
    k_mma2<<<ggrid, 256, SMEM_BYTES, S1>>>(tp0, bsum0, xp, st0p, NN);
    k_bnrelu<<<xgrid, 256, 0, S1>>>(xp, nbf_p, st0p, gam + 1*FEAT, bet + 1*FEAT, NN, 1);
    rec(E_BNP0, S1);

    // ---- S0: layer0 disease chain ----
    wait(S0, E_SPLITS);
    Trip td0; td0.n = 2;
    td0.a[0] = nbf_d; td0.w[0] = W(0);
    td0.a[1] = mbf1;  td0.w[1] = W(1);
    k_mma2<<<ggrid, 256, SMEM_BYTES, S0>>>(td0, b1 + FEAT, xd, st0d, NN);
    k_bnrelu<<<xgrid, 256, 0, S0>>>(xd, nbf_d, st0d, gam + 0*FEAT, bet + 0*FEAT, NN, 1);
    rec(E_BND0, S0);

    // ---- S0: layer1 aggregates (protein side) ----
    wait(S0, E_BNP0);                       // also covers WAR on mbf0/2/3 vs pGEMM_l0
    k_aggregate<<<NN, 128, 0, S0>>>(mbf0, xd, 0);
    rec(E_M0, S0);
    k_aggregate<<<NN, 128, 0, S0>>>(mbf2, xp, 2);
    k_aggregate<<<NN, 128, 0, S0>>>(mbf3, xp, 3);

    // ---- S1: layer1 disease chain ----
    wait(S1, E_BND0);                       // nbf_d ready; WAR on mbf1 vs dGEMM_l0
    k_aggregate<<<NN, 128, 0, S1>>>(mbf1, xp, 1);
    rec(E_M1, S1);
    wait(S1, E_M0);                         // xd WAR: agg m0 reads xd before we overwrite it
    Trip td1; td1.n = 2;
    td1.a[0] = nbf_d; td1.w[0] = W(6);
    td1.a[1] = mbf1;  td1.w[1] = W(7);
    k_mma2<<<ggrid, 256, SMEM_BYTES, S1>>>(td1, b2 + FEAT, xd, st1d, NN);
    k_bnrelu<<<xgrid, 256, 0, S1>>>(xd, nbf_d, st1d, gam + 2*FEAT, bet + 2*FEAT, NN, 0);
    Trip tj1; tj1.n = 1; tj1.a[0] = nbf_d; tj1.w[0] = W(12);
    k_mma2<<<ggrid, 256, SMEM_BYTES, S1>>>(tj1, pbd, out, nullptr, NN);
    rec(E_S1, S1);

    // ---- S0: layer1 protein chain + projection ----
    wait(S0, E_M1);                         // xp WAR: agg m1 reads xp before we overwrite it
    Trip tp1; tp1.n = 4;
    tp1.a[0] = nbf_p; tp1.w[0] = W(8);
    tp1.a[1] = mbf0;  tp1.w[1] = W(9);
    tp1.a[2] = mbf2;  tp1.w[2] = W(10);
    tp1.a[3] = mbf3;  tp1.w[3] = W(11);
    k_mma2<<<ggrid, 256, SMEM_BYTES, S0>>>(tp1, bsum1, xp, st1p, NN);
    k_bnrelu<<<xgrid, 256, 0, S0>>>(xp, nbf_p, st1p, gam + 3*FEAT, bet + 3*FEAT, NN, 0);
    Trip tj2; tj2.n = 1; tj2.a[0] = nbf_p; tj2.w[0] = W(13);
    k_mma2<<<ggrid, 256, SMEM_BYTES, S0>>>(tj2, pbp, out + (size_t)NN*FEAT, nullptr, NN);

    // join
    wait(S0, E_S1);
}

// round 6
// speedup vs baseline: 2.8196x; 1.0107x over previous
#include <cuda_runtime.h>
#include <cuda_bf16.h>
#include <cstdint>
#include <cstddef>

#define NN 20000
#define FEAT 512
#define FF (FEAT*FEAT)
#define EE 320000
#define EPS 1e-5f
#define GY ((NN + 127) / 128)

// ---------------- scratch (device globals; no allocation allowed) ----------------
__device__ float g_x[2][NN*FEAT];                       // fp32 layer outputs
__device__ __nv_bfloat16 g_nbf[2][(size_t)NN*1024];     // node feats split [row][hi512|lo512]
__device__ __nv_bfloat16 g_mbf[4][(size_t)NN*1024];     // aggregate means split
__device__ __nv_bfloat16 g_wbf[14][(size_t)2*FF];       // weights split: [hi FF | lo FF], W[k][n]
__device__ float g_bsum[2][FEAT];
__device__ float g_stats[8*FEAT];   // L0: [sum_d|sq_d|sum_p|sq_p], L1: +4*FEAT
__device__ int   g_cnt[4][NN];
__device__ int   g_off[4][NN+1];
__device__ int   g_cur[4][NN];
__device__ int   g_srcid[4][EE];

// ---------------- small utils ----------------
__global__ void k_zero_int(int* p, int n) {
    int i = blockIdx.x*blockDim.x + threadIdx.x;
    if (i < n) p[i] = 0;
}
__global__ void k_zero_float(float* p, int n) {
    int i = blockIdx.x*blockDim.x + threadIdx.x;
    if (i < n) p[i] = 0.f;
}
__device__ __forceinline__ void bsplit(float x, __nv_bfloat16& h, __nv_bfloat16& l) {
    h = __float2bfloat16(x);
    l = __float2bfloat16(x - __bfloat162float(h));
}

// ---------------- CSR build ----------------
__global__ void k_count(const int* __restrict__ a_src, const int* __restrict__ a_dst,
                        const int* __restrict__ i_src, const int* __restrict__ i_dst, int e) {
    int idx = blockIdx.x*blockDim.x + threadIdx.x;
    if (idx >= e) return;
    atomicAdd(&g_cnt[0][a_dst[idx]], 1);
    atomicAdd(&g_cnt[1][a_src[idx]], 1);
    atomicAdd(&g_cnt[2][i_dst[idx]], 1);
    atomicAdd(&g_cnt[3][i_src[idx]], 1);
}

__global__ void k_scan() {
    int r = blockIdx.x;
    int t = threadIdx.x;
    const int per = (NN + 1023) / 1024;
    __shared__ int part[1024];
    int base = t * per;
    int sum = 0;
    for (int i = 0; i < per; i++) { int idx = base + i; if (idx < NN) sum += g_cnt[r][idx]; }
    part[t] = sum;
    __syncthreads();
    for (int d = 1; d < 1024; d <<= 1) {
        int v = 0;
        if (t >= d) v = part[t-d];
        __syncthreads();
        if (t >= d) part[t] += v;
        __syncthreads();
    }
    int run = (t == 0) ? 0 : part[t-1];
    for (int i = 0; i < per; i++) {
        int idx = base + i;
        if (idx < NN) { g_off[r][idx] = run; g_cur[r][idx] = run; run += g_cnt[r][idx]; }
    }
    if (t == 1023) g_off[r][NN] = run;
}

__global__ void k_fill(const int* __restrict__ a_src, const int* __restrict__ a_dst,
                       const int* __restrict__ i_src, const int* __restrict__ i_dst, int e) {
    int idx = blockIdx.x*blockDim.x + threadIdx.x;
    if (idx >= e) return;
    int p;
    p = atomicAdd(&g_cur[0][a_dst[idx]], 1); g_srcid[0][p] = a_src[idx];
    p = atomicAdd(&g_cur[1][a_src[idx]], 1); g_srcid[1][p] = a_dst[idx];
    p = atomicAdd(&g_cur[2][i_dst[idx]], 1); g_srcid[2][p] = i_src[idx];
    p = atomicAdd(&g_cur[3][i_src[idx]], 1); g_srcid[3][p] = i_dst[idx];
}

// ---------------- splits ----------------
__global__ void k_splitX(__nv_bfloat16* __restrict__ dst, const float* __restrict__ src, int M) {
    int i = blockIdx.x*blockDim.x + threadIdx.x;
    if (i >= M*128) return;
    int r = i >> 7, c = (i & 127) * 4;
    float4 v = *(const float4*)(src + (size_t)r*FEAT + c);
    float xv[4] = {v.x, v.y, v.z, v.w};
    __nv_bfloat16 h[4], l[4];
    #pragma unroll
    for (int j = 0; j < 4; j++) bsplit(xv[j], h[j], l[j]);
    size_t base = (size_t)r*1024 + c;
    __nv_bfloat162 t2;
    t2.x=h[0]; t2.y=h[1]; *(__nv_bfloat162*)(dst+base)     = t2;
    t2.x=h[2]; t2.y=h[3]; *(__nv_bfloat162*)(dst+base+2)   = t2;
    t2.x=l[0]; t2.y=l[1]; *(__nv_bfloat162*)(dst+base+512) = t2;
    t2.x=l[2]; t2.y=l[3]; *(__nv_bfloat162*)(dst+base+514) = t2;
}

__global__ void k_splitW(__nv_bfloat16* __restrict__ dst, const float* __restrict__ src) {
    int i = blockIdx.x*blockDim.x + threadIdx.x;
    if (i >= FF) return;
    __nv_bfloat16 h, l;
    bsplit(src[i], h, l);
    dst[i] = h; dst[FF + i] = l;
}

__global__ void k_combineSplit(__nv_bfloat16* __restrict__ dst,
                               const float* __restrict__ Ws, const float* __restrict__ b,
                               float* __restrict__ bsum) {
    int i = blockIdx.x*blockDim.x + threadIdx.x;
    if (i < FF) {
        float x = Ws[i] + Ws[2*(size_t)FF + i] + Ws[3*(size_t)FF + i];
        __nv_bfloat16 h, l; bsplit(x, h, l);
        dst[i] = h; dst[FF + i] = l;
    }
    if (i < FEAT) bsum[i] = b[i] + b[2*FEAT + i] + b[3*FEAT + i];
}

// ---------------- aggregation ----------------
__global__ void k_aggregate(__nv_bfloat16* __restrict__ outbf, const float* __restrict__ hsrc, int rel) {
    int node = blockIdx.x;
    int t = threadIdx.x;  // 0..127
    int beg = g_off[rel][node];
    int end = g_off[rel][node+1];
    float ax = 0.f, ay = 0.f, az = 0.f, aw = 0.f;
    for (int j = beg; j < end; j++) {
        int s = g_srcid[rel][j];
        float4 v = __ldg((const float4*)(hsrc + (size_t)s*FEAT) + t);
        ax += v.x; ay += v.y; az += v.z; aw += v.w;
    }
    float inv = (end > beg) ? 1.f / (float)(end - beg) : 0.f;
    float m[4] = {ax*inv, ay*inv, az*inv, aw*inv};
    __nv_bfloat16 h[4], l[4];
    #pragma unroll
    for (int j = 0; j < 4; j++) bsplit(m[j], h[j], l[j]);
    size_t base = (size_t)node*1024 + t*4;
    __nv_bfloat162 t2;
    t2.x=h[0]; t2.y=h[1]; *(__nv_bfloat162*)(outbf+base)     = t2;
    t2.x=h[2]; t2.y=h[3]; *(__nv_bfloat162*)(outbf+base+2)   = t2;
    t2.x=l[0]; t2.y=l[1]; *(__nv_bfloat162*)(outbf+base+512) = t2;
    t2.x=l[2]; t2.y=l[3]; *(__nv_bfloat162*)(outbf+base+514) = t2;
}

// ---------------- tensor-core GEMM (split-triples, optional accumulate + fused stats) ----------------
struct Trip {
    const __nv_bfloat16* a[4];
    const __nv_bfloat16* w[4];
    int n;
};

__device__ __forceinline__ uint32_t sptr(const void* p) {
    return (uint32_t)__cvta_generic_to_shared(p);
}
__device__ __forceinline__ void cpa16(uint32_t sa, const void* g, bool pred) {
    int sz = pred ? 16 : 0;
    asm volatile("cp.async.cg.shared.global [%0], [%1], 16, %2;\n" :: "r"(sa), "l"(g), "r"(sz));
}

#define APAD 40
#define BPAD 136
#define A_ELEMS (128*APAD)
#define B_ELEMS (32*BPAD)
#define OFF_AH(buf) ((buf)*A_ELEMS)
#define OFF_AL(buf) (2*A_ELEMS + (buf)*A_ELEMS)
#define OFF_BH(buf) (4*A_ELEMS + (buf)*B_ELEMS)
#define OFF_BL(buf) (4*A_ELEMS + 2*B_ELEMS + (buf)*B_ELEMS)
#define SMEM_ELEMS (4*A_ELEMS + 4*B_ELEMS)
#define SMEM_BYTES (SMEM_ELEMS*2)

__global__ __launch_bounds__(256, 2)
void k_mma2(const Trip trip, const float* __restrict__ bias, float* __restrict__ C,
            float* __restrict__ stats, int M, int accum)
{
    extern __shared__ __align__(16) __nv_bfloat16 sm[];

    const int tid  = threadIdx.x;
    const int lane = tid & 31;
    const int warp = tid >> 5;
    const int wm = (warp & 1) * 64;
    const int wn = (warp >> 1) * 32;
    const int row0 = blockIdx.y * 128;
    const int col0 = blockIdx.x * 128;

    float acc[4][4][4];
    #pragma unroll
    for (int i = 0; i < 4; i++)
        #pragma unroll
        for (int j = 0; j < 4; j++)
            #pragma unroll
            for (int k = 0; k < 4; k++) acc[i][j][k] = 0.f;

    const int T = trip.n * 16;

    auto issue = [&](int t, int buf) {
        int s  = t >> 4;
        int k0 = (t & 15) * 32;
        const __nv_bfloat16* A = trip.a[s];
        const __nv_bfloat16* W = trip.w[s];
        int ar = tid >> 2;
        int ac = (tid & 3) * 8;
        #pragma unroll
        for (int h = 0; h < 2; h++) {
            int r = ar + h*64;
            int gr = row0 + r;
            bool p = gr < M;
            const __nv_bfloat16* gp = A + (size_t)gr*1024 + k0 + ac;
            cpa16(sptr(sm + OFF_AH(buf) + r*APAD + ac), gp, p);
            cpa16(sptr(sm + OFF_AL(buf) + r*APAD + ac), gp + 512, p);
        }
        int br = tid >> 4;
        int bc = (tid & 15) * 8;
        #pragma unroll
        for (int h = 0; h < 2; h++) {
            int r = br + h*16;
            const __nv_bfloat16* gp = W + (size_t)(k0 + r)*512 + col0 + bc;
            cpa16(sptr(sm + OFF_BH(buf) + r*BPAD + bc), gp, true);
            cpa16(sptr(sm + OFF_BL(buf) + r*BPAD + bc), gp + FF, true);
        }
        asm volatile("cp.async.commit_group;\n" ::: "memory");
    };

    issue(0, 0);

    const int g2 = lane >> 3, lr = lane & 7;

    for (int t = 0; t < T; t++) {
        int buf = t & 1;
        asm volatile("cp.async.wait_group 0;\n" ::: "memory");
        __syncthreads();
        if (t + 1 < T) issue(t + 1, buf ^ 1);

        #pragma unroll
        for (int ks = 0; ks < 2; ks++) {
            int arow = wm + (g2 & 1)*8 + lr;
            int acol = ks*16 + (g2 >> 1)*8;
            uint32_t ah[4][4], al[4][4];
            #pragma unroll
            for (int mi = 0; mi < 4; mi++) {
                uint32_t adh = sptr(sm + OFF_AH(buf) + (arow + mi*16)*APAD + acol);
                asm volatile("ldmatrix.sync.aligned.m8n8.x4.shared.b16 {%0,%1,%2,%3}, [%4];\n"
                    : "=r"(ah[mi][0]), "=r"(ah[mi][1]), "=r"(ah[mi][2]), "=r"(ah[mi][3])
                    : "r"(adh));
                uint32_t adl = sptr(sm + OFF_AL(buf) + (arow + mi*16)*APAD + acol);
                asm volatile("ldmatrix.sync.aligned.m8n8.x4.shared.b16 {%0,%1,%2,%3}, [%4];\n"
                    : "=r"(al[mi][0]), "=r"(al[mi][1]), "=r"(al[mi][2]), "=r"(al[mi][3])
                    : "r"(adl));
            }
            int brow = ks*16 + (g2 & 1)*8 + lr;
            uint32_t bh[2][4], bl[2][4];
            #pragma unroll
            for (int nj = 0; nj < 2; nj++) {
                int bcol = wn + nj*16 + (g2 >> 1)*8;
                uint32_t bdh = sptr(sm + OFF_BH(buf) + brow*BPAD + bcol);
                asm volatile("ldmatrix.sync.aligned.m8n8.x4.trans.shared.b16 {%0,%1,%2,%3}, [%4];\n"
                    : "=r"(bh[nj][0]), "=r"(bh[nj][1]), "=r"(bh[nj][2]), "=r"(bh[nj][3])
                    : "r"(bdh));
                uint32_t bdl = sptr(sm + OFF_BL(buf) + brow*BPAD + bcol);
                asm volatile("ldmatrix.sync.aligned.m8n8.x4.trans.shared.b16 {%0,%1,%2,%3}, [%4];\n"
                    : "=r"(bl[nj][0]), "=r"(bl[nj][1]), "=r"(bl[nj][2]), "=r"(bl[nj][3])
                    : "r"(bdl));
            }
            #pragma unroll
            for (int mi = 0; mi < 4; mi++)
                #pragma unroll
                for (int ni = 0; ni < 4; ni++) {
                    uint32_t b0h = bh[ni >> 1][(ni & 1)*2];
                    uint32_t b1h = bh[ni >> 1][(ni & 1)*2 + 1];
                    uint32_t b0l = bl[ni >> 1][(ni & 1)*2];
                    uint32_t b1l = bl[ni >> 1][(ni & 1)*2 + 1];
                    asm volatile(
                        "mma.sync.aligned.m16n8k16.row.col.f32.bf16.bf16.f32 "
                        "{%0,%1,%2,%3}, {%4,%5,%6,%7}, {%8,%9}, {%0,%1,%2,%3};\n"
                        : "+f"(acc[mi][ni][0]), "+f"(acc[mi][ni][1]),
                          "+f"(acc[mi][ni][2]), "+f"(acc[mi][ni][3])
                        : "r"(ah[mi][0]), "r"(ah[mi][1]), "r"(ah[mi][2]), "r"(ah[mi][3]),
                          "r"(b0h), "r"(b1h));
                    asm volatile(
                        "mma.sync.aligned.m16n8k16.row.col.f32.bf16.bf16.f32 "
                        "{%0,%1,%2,%3}, {%4,%5,%6,%7}, {%8,%9}, {%0,%1,%2,%3};\n"
                        : "+f"(acc[mi][ni][0]), "+f"(acc[mi][ni][1]),
                          "+f"(acc[mi][ni][2]), "+f"(acc[mi][ni][3])
                        : "r"(al[mi][0]), "r"(al[mi][1]), "r"(al[mi][2]), "r"(al[mi][3]),
                          "r"(b0h), "r"(b1h));
                    asm volatile(
                        "mma.sync.aligned.m16n8k16.row.col.f32.bf16.bf16.f32 "
                        "{%0,%1,%2,%3}, {%4,%5,%6,%7}, {%8,%9}, {%0,%1,%2,%3};\n"
                        : "+f"(acc[mi][ni][0]), "+f"(acc[mi][ni][1]),
                          "+f"(acc[mi][ni][2]), "+f"(acc[mi][ni][3])
                        : "r"(ah[mi][0]), "r"(ah[mi][1]), "r"(ah[mi][2]), "r"(ah[mi][3]),
                          "r"(b0l), "r"(b1l));
                }
        }
    }

    // epilogue: (accumulate|bias) + store + optional fused column stats
    float vsum[4][2], vsq[4][2];
    #pragma unroll
    for (int ni = 0; ni < 4; ni++) { vsum[ni][0]=vsum[ni][1]=vsq[ni][0]=vsq[ni][1]=0.f; }

    #pragma unroll
    for (int mi = 0; mi < 4; mi++) {
        int gr0 = row0 + wm + mi*16 + (lane >> 2);
        int gr1 = gr0 + 8;
        bool p0 = gr0 < M, p1 = gr1 < M;
        #pragma unroll
        for (int ni = 0; ni < 4; ni++) {
            int gc = col0 + wn + ni*8 + (lane & 3)*2;
            float a00 = acc[mi][ni][0], a01 = acc[mi][ni][1];
            float a10 = acc[mi][ni][2], a11 = acc[mi][ni][3];
            if (accum) {
                if (p0) {
                    float2 c0 = *(float2*)(C + (size_t)gr0*FEAT + gc);
                    a00 += c0.x; a01 += c0.y;
                }
                if (p1) {
                    float2 c1 = *(float2*)(C + (size_t)gr1*FEAT + gc);
                    a10 += c1.x; a11 += c1.y;
                }
            } else {
                float b0 = bias[gc], b1 = bias[gc+1];
                a00 += b0; a01 += b1; a10 += b0; a11 += b1;
            }
            if (p0) {
                float2 o; o.x = a00; o.y = a01;
                *(float2*)(C + (size_t)gr0*FEAT + gc) = o;
                vsum[ni][0] += a00; vsq[ni][0] += a00*a00;
                vsum[ni][1] += a01; vsq[ni][1] += a01*a01;
            }
            if (p1) {
                float2 o; o.x = a10; o.y = a11;
                *(float2*)(C + (size_t)gr1*FEAT + gc) = o;
                vsum[ni][0] += a10; vsq[ni][0] += a10*a10;
                vsum[ni][1] += a11; vsq[ni][1] += a11*a11;
            }
        }
    }

    if (stats) {
        #pragma unroll
        for (int ni = 0; ni < 4; ni++) {
            #pragma unroll
            for (int j = 0; j < 2; j++) {
                float s = vsum[ni][j], q = vsq[ni][j];
                #pragma unroll
                for (int st = 4; st < 32; st <<= 1) {
                    s += __shfl_xor_sync(0xFFFFFFFFu, s, st);
                    q += __shfl_xor_sync(0xFFFFFFFFu, q, st);
                }
                if (lane < 4) {
                    int c = col0 + wn + ni*8 + lane*2 + j;
                    atomicAdd(&stats[c], s);
                    atomicAdd(&stats[FEAT + c], q);
                }
            }
        }
    }
}

// ---------------- BatchNorm (apply) ----------------
__global__ void k_bnrelu(float* __restrict__ X, __nv_bfloat16* __restrict__ Xbf,
                         const float* __restrict__ stats,
                         const float* __restrict__ gamma, const float* __restrict__ beta,
                         int M, int writeF32) {
    int i = blockIdx.x*blockDim.x + threadIdx.x;
    if (i >= M*128) return;
    int r = i >> 7, c = (i & 127) * 4;
    float invM = 1.f / (float)M;
    float4 x = *(float4*)(X + (size_t)r*FEAT + c);
    float xv[4] = {x.x, x.y, x.z, x.w};
    float y[4];
    #pragma unroll
    for (int j = 0; j < 4; j++) {
        int cc = c + j;
        float mean = stats[cc] * invM;
        float var  = stats[FEAT + cc] * invM - mean*mean;
        float v = gamma[cc] * (xv[j] - mean) * rsqrtf(var + EPS) + beta[cc];
        y[j] = v > 0.f ? v : 0.f;
    }
    if (writeF32) {
        float4 o = {y[0], y[1], y[2], y[3]};
        *(float4*)(X + (size_t)r*FEAT + c) = o;
    }
    __nv_bfloat16 h[4], l[4];
    #pragma unroll
    for (int j = 0; j < 4; j++) bsplit(y[j], h[j], l[j]);
    size_t base = (size_t)r*1024 + c;
    __nv_bfloat162 t2;
    t2.x=h[0]; t2.y=h[1]; *(__nv_bfloat162*)(Xbf+base)     = t2;
    t2.x=h[2]; t2.y=h[3]; *(__nv_bfloat162*)(Xbf+base+2)   = t2;
    t2.x=l[0]; t2.y=l[1]; *(__nv_bfloat162*)(Xbf+base+512) = t2;
    t2.x=l[2]; t2.y=l[3]; *(__nv_bfloat162*)(Xbf+base+514) = t2;
}

// ---------------- host ----------------
static void* sym(const void* s) { void* p = nullptr; cudaGetSymbolAddress(&p, s); return p; }

struct StreamCtx {
    cudaStream_t s1;
    cudaEvent_t ev[10];
    bool ok;
    StreamCtx() {
        ok = (cudaStreamCreateWithFlags(&s1, cudaStreamNonBlocking) == cudaSuccess);
        for (int i = 0; i < 10; i++)
            if (cudaEventCreateWithFlags(&ev[i], cudaEventDisableTiming) != cudaSuccess) ok = false;
    }
};

enum { E_START=0, E_AGG0, E_PSELF, E_BND0, E_BNP0, E_M0P, E_M1P, E_S1 };

extern "C" void kernel_launch(void* const* d_in, const int* in_sizes, int n_in,
                              void* d_out, int out_size)
{
    static StreamCtx ctx;

    const float* h_d  = (const float*)d_in[0];
    const float* h_p  = (const float*)d_in[1];
    const float* Ws1  = (const float*)d_in[2];
    const float* Wn1  = (const float*)d_in[3];
    const float* b1   = (const float*)d_in[4];
    const float* Ws2  = (const float*)d_in[5];
    const float* Wn2  = (const float*)d_in[6];
    const float* b2   = (const float*)d_in[7];
    const float* gam  = (const float*)d_in[8];
    const float* bet  = (const float*)d_in[9];
    const float* pWd  = (const float*)d_in[10];
    const float* pbd  = (const float*)d_in[11];
    const float* pWp  = (const float*)d_in[12];
    const float* pbp  = (const float*)d_in[13];
    const int*  a_src = (const int*)d_in[14];
    const int*  a_dst = (const int*)d_in[15];
    const int*  i_src = (const int*)d_in[16];
    const int*  i_dst = (const int*)d_in[17];
    float* out = (float*)d_out;
    const int e = in_sizes[14];

    float* xd    = (float*)sym(g_x);
    float* xp    = xd + (size_t)NN*FEAT;
    __nv_bfloat16* nbf_d = (__nv_bfloat16*)sym(g_nbf);
    __nv_bfloat16* nbf_p = nbf_d + (size_t)NN*1024;
    __nv_bfloat16* mbf   = (__nv_bfloat16*)sym(g_mbf);
    __nv_bfloat16* mbf0  = mbf;
    __nv_bfloat16* mbf1  = mbf + 1*(size_t)NN*1024;
    __nv_bfloat16* mbf2  = mbf + 2*(size_t)NN*1024;
    __nv_bfloat16* mbf3  = mbf + 3*(size_t)NN*1024;
    __nv_bfloat16* wbf   = (__nv_bfloat16*)sym(g_wbf);
    auto W = [&](int slot) { return wbf + (size_t)slot * 2 * FF; };
    float* bsum0 = (float*)sym(g_bsum);
    float* bsum1 = bsum0 + FEAT;
    float* st    = (float*)sym(g_stats);
    float* st0d = st, *st0p = st + 2*FEAT, *st1d = st + 4*FEAT, *st1p = st + 6*FEAT;
    int*   cnt   = (int*)sym(g_cnt);

    cudaFuncSetAttribute(k_mma2, cudaFuncAttributeMaxDynamicSharedMemorySize, SMEM_BYTES);

    const bool ok = ctx.ok;
    cudaStream_t S0 = 0;
    cudaStream_t S1 = ok ? ctx.s1 : (cudaStream_t)0;
    auto rec  = [&](int i, cudaStream_t s) { if (ok) cudaEventRecord(ctx.ev[i], s); };
    auto wait = [&](cudaStream_t s, int i)  { if (ok) cudaStreamWaitEvent(s, ctx.ev[i], 0); };

    int xgrid = (NN*128 + 255)/256;
    int wgrid = (FF + 255)/256;
    dim3 ggrid(4, GY);

    auto gemm = [&](cudaStream_t s, const __nv_bfloat16* A0, const __nv_bfloat16* W0,
                    const float* bias, float* C, float* stats, int accum,
                    const __nv_bfloat16* A1 = nullptr, const __nv_bfloat16* W1 = nullptr,
                    const __nv_bfloat16* A2 = nullptr, const __nv_bfloat16* W2p = nullptr) {
        Trip t; t.n = 1;
        t.a[0] = A0; t.w[0] = W0;
        if (A1) { t.a[t.n] = A1; t.w[t.n] = W1; t.n++; }
        if (A2) { t.a[t.n] = A2; t.w[t.n] = W2p; t.n++; }
        k_mma2<<<ggrid, 256, SMEM_BYTES, s>>>(t, bias, C, stats, NN, accum);
    };

    // fork
    rec(E_START, S0);
    wait(S1, E_START);

    // ---- S0: CSR build + all layer0 aggregates ----
    k_zero_int<<<(4*NN + 255)/256, 256, 0, S0>>>(cnt, 4*NN);
    k_count<<<(e + 255)/256, 256, 0, S0>>>(a_src, a_dst, i_src, i_dst, e);
    k_scan<<<4, 1024, 0, S0>>>();
    k_fill<<<(e + 255)/256, 256, 0, S0>>>(a_src, a_dst, i_src, i_dst, e);
    k_aggregate<<<NN, 128, 0, S0>>>(mbf1, h_p, 1);
    k_aggregate<<<NN, 128, 0, S0>>>(mbf0, h_d, 0);
    k_aggregate<<<NN, 128, 0, S0>>>(mbf2, h_p, 2);
    k_aggregate<<<NN, 128, 0, S0>>>(mbf3, h_p, 3);
    rec(E_AGG0, S0);

    // ---- S1: splits, then self-GEMMs (no aggregate dependency) ----
    k_splitX<<<xgrid, 256, 0, S1>>>(nbf_p, h_p, NN);
    k_splitX<<<xgrid, 256, 0, S1>>>(nbf_d, h_d, NN);
    k_combineSplit<<<wgrid, 256, 0, S1>>>(W(2), Ws1, b1, bsum0);
    k_splitW<<<wgrid, 256, 0, S1>>>(W(0),  Ws1 + (size_t)FF);
    k_splitW<<<wgrid, 256, 0, S1>>>(W(1),  Wn1 + (size_t)FF);
    k_splitW<<<wgrid, 256, 0, S1>>>(W(3),  Wn1);
    k_splitW<<<wgrid, 256, 0, S1>>>(W(4),  Wn1 + 2*(size_t)FF);
    k_splitW<<<wgrid, 256, 0, S1>>>(W(5),  Wn1 + 3*(size_t)FF);
    k_splitW<<<wgrid, 256, 0, S1>>>(W(6),  Ws2 + (size_t)FF);
    k_splitW<<<wgrid, 256, 0, S1>>>(W(7),  Wn2 + (size_t)FF);
    k_combineSplit<<<wgrid, 256, 0, S1>>>(W(8), Ws2, b2, bsum1);
    k_splitW<<<wgrid, 256, 0, S1>>>(W(9),  Wn2);
    k_splitW<<<wgrid, 256, 0, S1>>>(W(10), Wn2 + 2*(size_t)FF);
    k_splitW<<<wgrid, 256, 0, S1>>>(W(11), Wn2 + 3*(size_t)FF);
    k_splitW<<<wgrid, 256, 0, S1>>>(W(12), pWd);
    k_splitW<<<wgrid, 256, 0, S1>>>(W(13), pWp);
    k_zero_float<<<(8*FEAT + 255)/256, 256, 0, S1>>>(st, 8*FEAT);

    // layer0 self passes (S1)
    gemm(S1, nbf_p, W(2), bsum0,    xp, nullptr, 0);                 // protein self
    rec(E_PSELF, S1);
    gemm(S1, nbf_d, W(0), b1 + FEAT, xd, nullptr, 0);                // disease self

    // layer0 disease neigh (S1, needs agg m1)
    wait(S1, E_AGG0);
    gemm(S1, mbf1, W(1), nullptr, xd, st0d, 1);
    k_bnrelu<<<xgrid, 256, 0, S1>>>(xd, nbf_d, st0d, gam + 0*FEAT, bet + 0*FEAT, NN, 1);
    rec(E_BND0, S1);

    // layer0 protein neigh (S0, needs aggs (in-order) + xp from self pass)
    wait(S0, E_PSELF);
    gemm(S0, mbf0, W(3), nullptr, xp, st0p, 1, mbf2, W(4), mbf3, W(5));
    k_bnrelu<<<xgrid, 256, 0, S0>>>(xp, nbf_p, st0p, gam + 1*FEAT, bet + 1*FEAT, NN, 1);
    rec(E_BNP0, S0);

    // ---- layer1 aggregates ----
    // S0: m0' from xd (needs E_BND0; WAR mbf0 vs pneigh_L0 in-order on S0)
    wait(S0, E_BND0);
    k_aggregate<<<NN, 128, 0, S0>>>(mbf0, xd, 0);
    rec(E_M0P, S0);
    k_aggregate<<<NN, 128, 0, S0>>>(mbf2, xp, 2);
    k_aggregate<<<NN, 128, 0, S0>>>(mbf3, xp, 3);

    // S1: m1' from xp (needs E_BNP0; WAR mbf1 vs dneigh_L0 in-order on S1)
    wait(S1, E_BNP0);
    k_aggregate<<<NN, 128, 0, S1>>>(mbf1, xp, 1);
    rec(E_M1P, S1);

    // ---- S1: layer1 disease chain + projection ----
    wait(S1, E_M0P);                 // xd WAR: m0' reads xd before overwrite
    gemm(S1, nbf_d, W(6), b2 + FEAT, xd, nullptr, 0);
    gemm(S1, mbf1,  W(7), nullptr,   xd, st1d, 1);
    k_bnrelu<<<xgrid, 256, 0, S1>>>(xd, nbf_d, st1d, gam + 2*FEAT, bet + 2*FEAT, NN, 0);
    gemm(S1, nbf_d, W(12), pbd, out, nullptr, 0);
    rec(E_S1, S1);

    // ---- S0: layer1 protein chain + projection ----
    wait(S0, E_M1P);                 // xp WAR: m1' reads xp before overwrite
    gemm(S0, nbf_p, W(8), bsum1, xp, nullptr, 0);
    gemm(S0, mbf0,  W(9), nullptr, xp, st1p, 1, mbf2, W(10), mbf3, W(11));
    k_bnrelu<<<xgrid, 256, 0, S0>>>(xp, nbf_p, st1p, gam + 3*FEAT, bet + 3*FEAT, NN, 0);
    gemm(S0, nbf_p, W(13), pbp, out + (size_t)NN*FEAT, nullptr, 0);

    // join
    wait(S0, E_S1);
}

// round 7
// speedup vs baseline: 2.8713x; 1.0183x over previous
#include <cuda_runtime.h>
#include <cuda_bf16.h>
#include <cuda_fp16.h>
#include <cstdint>
#include <cstddef>

#define NN 20000
#define FEAT 512
#define FF (FEAT*FEAT)
#define EE 320000
#define EPS 1e-5f
#define GY ((NN + 127) / 128)

// ---------------- scratch (device globals; no allocation allowed) ----------------
__device__ float g_x[2][NN*FEAT];                       // fp32 layer outputs (BN input only)
__device__ __half g_h16[2][(size_t)NN*FEAT];            // fp16 aggregate-gather sources
__device__ __nv_bfloat16 g_nbf[2][(size_t)NN*1024];     // node feats split [row][hi512|lo512]
__device__ __nv_bfloat16 g_mbf[4][(size_t)NN*1024];     // aggregate means split
__device__ __nv_bfloat16 g_wbf[14][(size_t)2*FF];       // weights split: [hi FF | lo FF]
__device__ float g_bsum[2][FEAT];
__device__ float g_stats[8*FEAT];
__device__ int   g_cnt[4][NN];
__device__ int   g_off[4][NN+1];
__device__ int   g_cur[4][NN];
__device__ int   g_srcid[4][EE];

// ---------------- small utils ----------------
__global__ void k_zero_int(int* p, int n) {
    int i = blockIdx.x*blockDim.x + threadIdx.x;
    if (i < n) p[i] = 0;
}
__global__ void k_zero_float(float* p, int n) {
    int i = blockIdx.x*blockDim.x + threadIdx.x;
    if (i < n) p[i] = 0.f;
}
__device__ __forceinline__ void bsplit(float x, __nv_bfloat16& h, __nv_bfloat16& l) {
    h = __float2bfloat16(x);
    l = __float2bfloat16(x - __bfloat162float(h));
}

// ---------------- CSR build ----------------
__global__ void k_count(const int* __restrict__ a_src, const int* __restrict__ a_dst,
                        const int* __restrict__ i_src, const int* __restrict__ i_dst, int e) {
    int idx = blockIdx.x*blockDim.x + threadIdx.x;
    if (idx >= e) return;
    atomicAdd(&g_cnt[0][a_dst[idx]], 1);
    atomicAdd(&g_cnt[1][a_src[idx]], 1);
    atomicAdd(&g_cnt[2][i_dst[idx]], 1);
    atomicAdd(&g_cnt[3][i_src[idx]], 1);
}

__global__ void k_scan() {
    int r = blockIdx.x;
    int t = threadIdx.x;
    const int per = (NN + 1023) / 1024;
    __shared__ int part[1024];
    int base = t * per;
    int sum = 0;
    for (int i = 0; i < per; i++) { int idx = base + i; if (idx < NN) sum += g_cnt[r][idx]; }
    part[t] = sum;
    __syncthreads();
    for (int d = 1; d < 1024; d <<= 1) {
        int v = 0;
        if (t >= d) v = part[t-d];
        __syncthreads();
        if (t >= d) part[t] += v;
        __syncthreads();
    }
    int run = (t == 0) ? 0 : part[t-1];
    for (int i = 0; i < per; i++) {
        int idx = base + i;
        if (idx < NN) { g_off[r][idx] = run; g_cur[r][idx] = run; run += g_cnt[r][idx]; }
    }
    if (t == 1023) g_off[r][NN] = run;
}

__global__ void k_fill(const int* __restrict__ a_src, const int* __restrict__ a_dst,
                       const int* __restrict__ i_src, const int* __restrict__ i_dst, int e) {
    int idx = blockIdx.x*blockDim.x + threadIdx.x;
    if (idx >= e) return;
    int p;
    p = atomicAdd(&g_cur[0][a_dst[idx]], 1); g_srcid[0][p] = a_src[idx];
    p = atomicAdd(&g_cur[1][a_src[idx]], 1); g_srcid[1][p] = a_dst[idx];
    p = atomicAdd(&g_cur[2][i_dst[idx]], 1); g_srcid[2][p] = i_src[idx];
    p = atomicAdd(&g_cur[3][i_src[idx]], 1); g_srcid[3][p] = i_dst[idx];
}

// ---------------- splits ----------------
// fp32 -> split bf16 (for GEMM A) + fp16 copy (for aggregation gather)
__global__ void k_splitX(__nv_bfloat16* __restrict__ dst, __half* __restrict__ dst16,
                         const float* __restrict__ src, int M) {
    int i = blockIdx.x*blockDim.x + threadIdx.x;
    if (i >= M*128) return;
    int r = i >> 7, c = (i & 127) * 4;
    float4 v = *(const float4*)(src + (size_t)r*FEAT + c);
    float xv[4] = {v.x, v.y, v.z, v.w};
    __nv_bfloat16 h[4], l[4];
    #pragma unroll
    for (int j = 0; j < 4; j++) bsplit(xv[j], h[j], l[j]);
    size_t base = (size_t)r*1024 + c;
    __nv_bfloat162 t2;
    t2.x=h[0]; t2.y=h[1]; *(__nv_bfloat162*)(dst+base)     = t2;
    t2.x=h[2]; t2.y=h[3]; *(__nv_bfloat162*)(dst+base+2)   = t2;
    t2.x=l[0]; t2.y=l[1]; *(__nv_bfloat162*)(dst+base+512) = t2;
    t2.x=l[2]; t2.y=l[3]; *(__nv_bfloat162*)(dst+base+514) = t2;
    __half2 p0 = __halves2half2(__float2half_rn(xv[0]), __float2half_rn(xv[1]));
    __half2 p1 = __halves2half2(__float2half_rn(xv[2]), __float2half_rn(xv[3]));
    *(__half2*)(dst16 + (size_t)r*FEAT + c)     = p0;
    *(__half2*)(dst16 + (size_t)r*FEAT + c + 2) = p1;
}

struct WJobs { const float* src[12]; __nv_bfloat16* dst[12]; };
__global__ void k_splitW12(WJobs jobs) {
    int slot = blockIdx.y;
    int i = blockIdx.x*blockDim.x + threadIdx.x;
    if (i >= FF) return;
    const float* src = jobs.src[slot];
    __nv_bfloat16* dst = jobs.dst[slot];
    __nv_bfloat16 h, l;
    bsplit(src[i], h, l);
    dst[i] = h; dst[FF + i] = l;
}

__global__ void k_combineSplit(__nv_bfloat16* __restrict__ dst,
                               const float* __restrict__ Ws, const float* __restrict__ b,
                               float* __restrict__ bsum) {
    int i = blockIdx.x*blockDim.x + threadIdx.x;
    if (i < FF) {
        float x = Ws[i] + Ws[2*(size_t)FF + i] + Ws[3*(size_t)FF + i];
        __nv_bfloat16 h, l; bsplit(x, h, l);
        dst[i] = h; dst[FF + i] = l;
    }
    if (i < FEAT) bsum[i] = b[i] + b[2*FEAT + i] + b[3*FEAT + i];
}

// ---------------- aggregation (fp16 gather, fp32 accumulate) ----------------
__global__ void k_aggregate(__nv_bfloat16* __restrict__ outbf, const __half* __restrict__ hsrc, int rel) {
    int node = blockIdx.x;
    int t = threadIdx.x;  // 0..127
    int beg = g_off[rel][node];
    int end = g_off[rel][node+1];
    float ax = 0.f, ay = 0.f, az = 0.f, aw = 0.f;
    for (int j = beg; j < end; j++) {
        int s = g_srcid[rel][j];
        uint2 v = __ldg((const uint2*)(hsrc + (size_t)s*FEAT) + t);
        __half2 h0 = *(__half2*)&v.x;
        __half2 h1 = *(__half2*)&v.y;
        float2 f0 = __half22float2(h0);
        float2 f1 = __half22float2(h1);
        ax += f0.x; ay += f0.y; az += f1.x; aw += f1.y;
    }
    float inv = (end > beg) ? 1.f / (float)(end - beg) : 0.f;
    float m[4] = {ax*inv, ay*inv, az*inv, aw*inv};
    __nv_bfloat16 h[4], l[4];
    #pragma unroll
    for (int j = 0; j < 4; j++) bsplit(m[j], h[j], l[j]);
    size_t base = (size_t)node*1024 + t*4;
    __nv_bfloat162 t2;
    t2.x=h[0]; t2.y=h[1]; *(__nv_bfloat162*)(outbf+base)     = t2;
    t2.x=h[2]; t2.y=h[3]; *(__nv_bfloat162*)(outbf+base+2)   = t2;
    t2.x=l[0]; t2.y=l[1]; *(__nv_bfloat162*)(outbf+base+512) = t2;
    t2.x=l[2]; t2.y=l[3]; *(__nv_bfloat162*)(outbf+base+514) = t2;
}

// ---------------- tensor-core GEMM (split-triples, optional accumulate + fused stats) ----------------
struct Trip {
    const __nv_bfloat16* a[4];
    const __nv_bfloat16* w[4];
    int n;
};

__device__ __forceinline__ uint32_t sptr(const void* p) {
    return (uint32_t)__cvta_generic_to_shared(p);
}
__device__ __forceinline__ void cpa16(uint32_t sa, const void* g, bool pred) {
    int sz = pred ? 16 : 0;
    asm volatile("cp.async.cg.shared.global [%0], [%1], 16, %2;\n" :: "r"(sa), "l"(g), "r"(sz));
}

#define APAD 40
#define BPAD 136
#define A_ELEMS (128*APAD)
#define B_ELEMS (32*BPAD)
#define OFF_AH(buf) ((buf)*A_ELEMS)
#define OFF_AL(buf) (2*A_ELEMS + (buf)*A_ELEMS)
#define OFF_BH(buf) (4*A_ELEMS + (buf)*B_ELEMS)
#define OFF_BL(buf) (4*A_ELEMS + 2*B_ELEMS + (buf)*B_ELEMS)
#define SMEM_ELEMS (4*A_ELEMS + 4*B_ELEMS)
#define SMEM_BYTES (SMEM_ELEMS*2)

__global__ __launch_bounds__(256, 2)
void k_mma2(const Trip trip, const float* __restrict__ bias, float* __restrict__ C,
            float* __restrict__ stats, int M, int accum)
{
    extern __shared__ __align__(16) __nv_bfloat16 sm[];

    const int tid  = threadIdx.x;
    const int lane = tid & 31;
    const int warp = tid >> 5;
    const int wm = (warp & 1) * 64;
    const int wn = (warp >> 1) * 32;
    const int row0 = blockIdx.y * 128;
    const int col0 = blockIdx.x * 128;

    float acc[4][4][4];
    #pragma unroll
    for (int i = 0; i < 4; i++)
        #pragma unroll
        for (int j = 0; j < 4; j++)
            #pragma unroll
            for (int k = 0; k < 4; k++) acc[i][j][k] = 0.f;

    const int T = trip.n * 16;

    auto issue = [&](int t, int buf) {
        int s  = t >> 4;
        int k0 = (t & 15) * 32;
        const __nv_bfloat16* A = trip.a[s];
        const __nv_bfloat16* W = trip.w[s];
        int ar = tid >> 2;
        int ac = (tid & 3) * 8;
        #pragma unroll
        for (int h = 0; h < 2; h++) {
            int r = ar + h*64;
            int gr = row0 + r;
            bool p = gr < M;
            const __nv_bfloat16* gp = A + (size_t)gr*1024 + k0 + ac;
            cpa16(sptr(sm + OFF_AH(buf) + r*APAD + ac), gp, p);
            cpa16(sptr(sm + OFF_AL(buf) + r*APAD + ac), gp + 512, p);
        }
        int br = tid >> 4;
        int bc = (tid & 15) * 8;
        #pragma unroll
        for (int h = 0; h < 2; h++) {
            int r = br + h*16;
            const __nv_bfloat16* gp = W + (size_t)(k0 + r)*512 + col0 + bc;
            cpa16(sptr(sm + OFF_BH(buf) + r*BPAD + bc), gp, true);
            cpa16(sptr(sm + OFF_BL(buf) + r*BPAD + bc), gp + FF, true);
        }
        asm volatile("cp.async.commit_group;\n" ::: "memory");
    };

    issue(0, 0);

    const int g2 = lane >> 3, lr = lane & 7;

    for (int t = 0; t < T; t++) {
        int buf = t & 1;
        asm volatile("cp.async.wait_group 0;\n" ::: "memory");
        __syncthreads();
        if (t + 1 < T) issue(t + 1, buf ^ 1);

        #pragma unroll
        for (int ks = 0; ks < 2; ks++) {
            int arow = wm + (g2 & 1)*8 + lr;
            int acol = ks*16 + (g2 >> 1)*8;
            uint32_t ah[4][4], al[4][4];
            #pragma unroll
            for (int mi = 0; mi < 4; mi++) {
                uint32_t adh = sptr(sm + OFF_AH(buf) + (arow + mi*16)*APAD + acol);
                asm volatile("ldmatrix.sync.aligned.m8n8.x4.shared.b16 {%0,%1,%2,%3}, [%4];\n"
                    : "=r"(ah[mi][0]), "=r"(ah[mi][1]), "=r"(ah[mi][2]), "=r"(ah[mi][3])
                    : "r"(adh));
                uint32_t adl = sptr(sm + OFF_AL(buf) + (arow + mi*16)*APAD + acol);
                asm volatile("ldmatrix.sync.aligned.m8n8.x4.shared.b16 {%0,%1,%2,%3}, [%4];\n"
                    : "=r"(al[mi][0]), "=r"(al[mi][1]), "=r"(al[mi][2]), "=r"(al[mi][3])
                    : "r"(adl));
            }
            int brow = ks*16 + (g2 & 1)*8 + lr;
            uint32_t bh[2][4], bl[2][4];
            #pragma unroll
            for (int nj = 0; nj < 2; nj++) {
                int bcol = wn + nj*16 + (g2 >> 1)*8;
                uint32_t bdh = sptr(sm + OFF_BH(buf) + brow*BPAD + bcol);
                asm volatile("ldmatrix.sync.aligned.m8n8.x4.trans.shared.b16 {%0,%1,%2,%3}, [%4];\n"
                    : "=r"(bh[nj][0]), "=r"(bh[nj][1]), "=r"(bh[nj][2]), "=r"(bh[nj][3])
                    : "r"(bdh));
                uint32_t bdl = sptr(sm + OFF_BL(buf) + brow*BPAD + bcol);
                asm volatile("ldmatrix.sync.aligned.m8n8.x4.trans.shared.b16 {%0,%1,%2,%3}, [%4];\n"
                    : "=r"(bl[nj][0]), "=r"(bl[nj][1]), "=r"(bl[nj][2]), "=r"(bl[nj][3])
                    : "r"(bdl));
            }
            #pragma unroll
            for (int mi = 0; mi < 4; mi++)
                #pragma unroll
                for (int ni = 0; ni < 4; ni++) {
                    uint32_t b0h = bh[ni >> 1][(ni & 1)*2];
                    uint32_t b1h = bh[ni >> 1][(ni & 1)*2 + 1];
                    uint32_t b0l = bl[ni >> 1][(ni & 1)*2];
                    uint32_t b1l = bl[ni >> 1][(ni & 1)*2 + 1];
                    asm volatile(
                        "mma.sync.aligned.m16n8k16.row.col.f32.bf16.bf16.f32 "
                        "{%0,%1,%2,%3}, {%4,%5,%6,%7}, {%8,%9}, {%0,%1,%2,%3};\n"
                        : "+f"(acc[mi][ni][0]), "+f"(acc[mi][ni][1]),
                          "+f"(acc[mi][ni][2]), "+f"(acc[mi][ni][3])
                        : "r"(ah[mi][0]), "r"(ah[mi][1]), "r"(ah[mi][2]), "r"(ah[mi][3]),
                          "r"(b0h), "r"(b1h));
                    asm volatile(
                        "mma.sync.aligned.m16n8k16.row.col.f32.bf16.bf16.f32 "
                        "{%0,%1,%2,%3}, {%4,%5,%6,%7}, {%8,%9}, {%0,%1,%2,%3};\n"
                        : "+f"(acc[mi][ni][0]), "+f"(acc[mi][ni][1]),
                          "+f"(acc[mi][ni][2]), "+f"(acc[mi][ni][3])
                        : "r"(al[mi][0]), "r"(al[mi][1]), "r"(al[mi][2]), "r"(al[mi][3]),
                          "r"(b0h), "r"(b1h));
                    asm volatile(
                        "mma.sync.aligned.m16n8k16.row.col.f32.bf16.bf16.f32 "
                        "{%0,%1,%2,%3}, {%4,%5,%6,%7}, {%8,%9}, {%0,%1,%2,%3};\n"
                        : "+f"(acc[mi][ni][0]), "+f"(acc[mi][ni][1]),
                          "+f"(acc[mi][ni][2]), "+f"(acc[mi][ni][3])
                        : "r"(ah[mi][0]), "r"(ah[mi][1]), "r"(ah[mi][2]), "r"(ah[mi][3]),
                          "r"(b0l), "r"(b1l));
                }
        }
    }

    // epilogue
    float vsum[4][2], vsq[4][2];
    #pragma unroll
    for (int ni = 0; ni < 4; ni++) { vsum[ni][0]=vsum[ni][1]=vsq[ni][0]=vsq[ni][1]=0.f; }

    #pragma unroll
    for (int mi = 0; mi < 4; mi++) {
        int gr0 = row0 + wm + mi*16 + (lane >> 2);
        int gr1 = gr0 + 8;
        bool p0 = gr0 < M, p1 = gr1 < M;
        #pragma unroll
        for (int ni = 0; ni < 4; ni++) {
            int gc = col0 + wn + ni*8 + (lane & 3)*2;
            float a00 = acc[mi][ni][0], a01 = acc[mi][ni][1];
            float a10 = acc[mi][ni][2], a11 = acc[mi][ni][3];
            if (accum) {
                if (p0) {
                    float2 c0 = *(float2*)(C + (size_t)gr0*FEAT + gc);
                    a00 += c0.x; a01 += c0.y;
                }
                if (p1) {
                    float2 c1 = *(float2*)(C + (size_t)gr1*FEAT + gc);
                    a10 += c1.x; a11 += c1.y;
                }
            } else {
                float b0 = bias[gc], b1 = bias[gc+1];
                a00 += b0; a01 += b1; a10 += b0; a11 += b1;
            }
            if (p0) {
                float2 o; o.x = a00; o.y = a01;
                *(float2*)(C + (size_t)gr0*FEAT + gc) = o;
                vsum[ni][0] += a00; vsq[ni][0] += a00*a00;
                vsum[ni][1] += a01; vsq[ni][1] += a01*a01;
            }
            if (p1) {
                float2 o; o.x = a10; o.y = a11;
                *(float2*)(C + (size_t)gr1*FEAT + gc) = o;
                vsum[ni][0] += a10; vsq[ni][0] += a10*a10;
                vsum[ni][1] += a11; vsq[ni][1] += a11*a11;
            }
        }
    }

    if (stats) {
        #pragma unroll
        for (int ni = 0; ni < 4; ni++) {
            #pragma unroll
            for (int j = 0; j < 2; j++) {
                float s = vsum[ni][j], q = vsq[ni][j];
                #pragma unroll
                for (int st = 4; st < 32; st <<= 1) {
                    s += __shfl_xor_sync(0xFFFFFFFFu, s, st);
                    q += __shfl_xor_sync(0xFFFFFFFFu, q, st);
                }
                if (lane < 4) {
                    int c = col0 + wn + ni*8 + lane*2 + j;
                    atomicAdd(&stats[c], s);
                    atomicAdd(&stats[FEAT + c], q);
                }
            }
        }
    }
}

// ---------------- BatchNorm (apply) ----------------
__global__ void k_bnrelu(float* __restrict__ X, __nv_bfloat16* __restrict__ Xbf,
                         __half* __restrict__ X16,
                         const float* __restrict__ stats,
                         const float* __restrict__ gamma, const float* __restrict__ beta, int M) {
    int i = blockIdx.x*blockDim.x + threadIdx.x;
    if (i >= M*128) return;
    int r = i >> 7, c = (i & 127) * 4;
    float invM = 1.f / (float)M;
    float4 x = *(float4*)(X + (size_t)r*FEAT + c);
    float xv[4] = {x.x, x.y, x.z, x.w};
    float y[4];
    #pragma unroll
    for (int j = 0; j < 4; j++) {
        int cc = c + j;
        float mean = stats[cc] * invM;
        float var  = stats[FEAT + cc] * invM - mean*mean;
        float v = gamma[cc] * (xv[j] - mean) * rsqrtf(var + EPS) + beta[cc];
        y[j] = v > 0.f ? v : 0.f;
    }
    if (X16) {
        __half2 p0 = __halves2half2(__float2half_rn(y[0]), __float2half_rn(y[1]));
        __half2 p1 = __halves2half2(__float2half_rn(y[2]), __float2half_rn(y[3]));
        *(__half2*)(X16 + (size_t)r*FEAT + c)     = p0;
        *(__half2*)(X16 + (size_t)r*FEAT + c + 2) = p1;
    }
    __nv_bfloat16 h[4], l[4];
    #pragma unroll
    for (int j = 0; j < 4; j++) bsplit(y[j], h[j], l[j]);
    size_t base = (size_t)r*1024 + c;
    __nv_bfloat162 t2;
    t2.x=h[0]; t2.y=h[1]; *(__nv_bfloat162*)(Xbf+base)     = t2;
    t2.x=h[2]; t2.y=h[3]; *(__nv_bfloat162*)(Xbf+base+2)   = t2;
    t2.x=l[0]; t2.y=l[1]; *(__nv_bfloat162*)(Xbf+base+512) = t2;
    t2.x=l[2]; t2.y=l[3]; *(__nv_bfloat162*)(Xbf+base+514) = t2;
}

// ---------------- host ----------------
static void* sym(const void* s) { void* p = nullptr; cudaGetSymbolAddress(&p, s); return p; }

struct StreamCtx {
    cudaStream_t s1;
    cudaEvent_t ev[8];
    bool ok;
    StreamCtx() {
        ok = (cudaStreamCreateWithFlags(&s1, cudaStreamNonBlocking) == cudaSuccess);
        for (int i = 0; i < 8; i++)
            if (cudaEventCreateWithFlags(&ev[i], cudaEventDisableTiming) != cudaSuccess) ok = false;
    }
};

enum { E_START=0, E_X16, E_M1, E_PSELF, E_BND0, E_BNP0, E_S1 };

extern "C" void kernel_launch(void* const* d_in, const int* in_sizes, int n_in,
                              void* d_out, int out_size)
{
    static StreamCtx ctx;

    const float* h_d  = (const float*)d_in[0];
    const float* h_p  = (const float*)d_in[1];
    const float* Ws1  = (const float*)d_in[2];
    const float* Wn1  = (const float*)d_in[3];
    const float* b1   = (const float*)d_in[4];
    const float* Ws2  = (const float*)d_in[5];
    const float* Wn2  = (const float*)d_in[6];
    const float* b2   = (const float*)d_in[7];
    const float* gam  = (const float*)d_in[8];
    const float* bet  = (const float*)d_in[9];
    const float* pWd  = (const float*)d_in[10];
    const float* pbd  = (const float*)d_in[11];
    const float* pWp  = (const float*)d_in[12];
    const float* pbp  = (const float*)d_in[13];
    const int*  a_src = (const int*)d_in[14];
    const int*  a_dst = (const int*)d_in[15];
    const int*  i_src = (const int*)d_in[16];
    const int*  i_dst = (const int*)d_in[17];
    float* out = (float*)d_out;
    const int e = in_sizes[14];

    float* xd    = (float*)sym(g_x);
    float* xp    = xd + (size_t)NN*FEAT;
    __half* h16d = (__half*)sym(g_h16);
    __half* h16p = h16d + (size_t)NN*FEAT;
    __nv_bfloat16* nbf_d = (__nv_bfloat16*)sym(g_nbf);
    __nv_bfloat16* nbf_p = nbf_d + (size_t)NN*1024;
    __nv_bfloat16* mbf   = (__nv_bfloat16*)sym(g_mbf);
    __nv_bfloat16* mbf0  = mbf;
    __nv_bfloat16* mbf1  = mbf + 1*(size_t)NN*1024;
    __nv_bfloat16* mbf2  = mbf + 2*(size_t)NN*1024;
    __nv_bfloat16* mbf3  = mbf + 3*(size_t)NN*1024;
    __nv_bfloat16* wbf   = (__nv_bfloat16*)sym(g_wbf);
    auto W = [&](int slot) { return wbf + (size_t)slot * 2 * FF; };
    float* bsum0 = (float*)sym(g_bsum);
    float* bsum1 = bsum0 + FEAT;
    float* st    = (float*)sym(g_stats);
    float* st0d = st, *st0p = st + 2*FEAT, *st1d = st + 4*FEAT, *st1p = st + 6*FEAT;
    int*   cnt   = (int*)sym(g_cnt);

    cudaFuncSetAttribute(k_mma2, cudaFuncAttributeMaxDynamicSharedMemorySize, SMEM_BYTES);

    const bool ok = ctx.ok;
    cudaStream_t S0 = 0;
    cudaStream_t S1 = ok ? ctx.s1 : (cudaStream_t)0;
    auto rec  = [&](int i, cudaStream_t s) { if (ok) cudaEventRecord(ctx.ev[i], s); };
    auto wait = [&](cudaStream_t s, int i)  { if (ok) cudaStreamWaitEvent(s, ctx.ev[i], 0); };

    int xgrid = (NN*128 + 255)/256;
    int wgrid = (FF + 255)/256;
    dim3 ggrid(4, GY);

    auto gemm = [&](cudaStream_t s, const __nv_bfloat16* A0, const __nv_bfloat16* W0,
                    const float* bias, float* C, float* stats, int accum,
                    const __nv_bfloat16* A1 = nullptr, const __nv_bfloat16* W1 = nullptr,
                    const __nv_bfloat16* A2 = nullptr, const __nv_bfloat16* W2p = nullptr) {
        Trip t; t.n = 1;
        t.a[0] = A0; t.w[0] = W0;
        if (A1) { t.a[t.n] = A1; t.w[t.n] = W1; t.n++; }
        if (A2) { t.a[t.n] = A2; t.w[t.n] = W2p; t.n++; }
        k_mma2<<<ggrid, 256, SMEM_BYTES, s>>>(t, bias, C, stats, NN, accum);
    };

    // fork
    rec(E_START, S0);
    wait(S1, E_START);

    // ---- S0: CSR build ----
    k_zero_int<<<(4*NN + 255)/256, 256, 0, S0>>>(cnt, 4*NN);
    k_count<<<(e + 255)/256, 256, 0, S0>>>(a_src, a_dst, i_src, i_dst, e);
    k_scan<<<4, 1024, 0, S0>>>();
    k_fill<<<(e + 255)/256, 256, 0, S0>>>(a_src, a_dst, i_src, i_dst, e);

    // ---- S1: input splits (produce fp16 gather sources) ----
    k_splitX<<<xgrid, 256, 0, S1>>>(nbf_p, h16p, h_p, NN);
    k_splitX<<<xgrid, 256, 0, S1>>>(nbf_d, h16d, h_d, NN);
    rec(E_X16, S1);

    // ---- S0: layer0 aggregates (fp16 gather) ----
    wait(S0, E_X16);
    k_aggregate<<<NN, 128, 0, S0>>>(mbf1, h16p, 1);
    rec(E_M1, S0);
    k_aggregate<<<NN, 128, 0, S0>>>(mbf0, h16d, 0);
    k_aggregate<<<NN, 128, 0, S0>>>(mbf2, h16p, 2);
    k_aggregate<<<NN, 128, 0, S0>>>(mbf3, h16p, 3);

    // ---- S1: weight splits + stats zero ----
    k_combineSplit<<<wgrid, 256, 0, S1>>>(W(2), Ws1, b1, bsum0);
    k_combineSplit<<<wgrid, 256, 0, S1>>>(W(8), Ws2, b2, bsum1);
    {
        WJobs jb;
        jb.src[0] = Ws1 + (size_t)FF;     jb.dst[0] = W(0);
        jb.src[1] = Wn1 + (size_t)FF;     jb.dst[1] = W(1);
        jb.src[2] = Wn1;                  jb.dst[2] = W(3);
        jb.src[3] = Wn1 + 2*(size_t)FF;   jb.dst[3] = W(4);
        jb.src[4] = Wn1 + 3*(size_t)FF;   jb.dst[4] = W(5);
        jb.src[5] = Ws2 + (size_t)FF;     jb.dst[5] = W(6);
        jb.src[6] = Wn2 + (size_t)FF;     jb.dst[6] = W(7);
        jb.src[7] = Wn2;                  jb.dst[7] = W(9);
        jb.src[8] = Wn2 + 2*(size_t)FF;   jb.dst[8] = W(10);
        jb.src[9] = Wn2 + 3*(size_t)FF;   jb.dst[9] = W(11);
        jb.src[10] = pWd;                 jb.dst[10] = W(12);
        jb.src[11] = pWp;                 jb.dst[11] = W(13);
        dim3 wg(wgrid, 12);
        k_splitW12<<<wg, 256, 0, S1>>>(jb);
    }
    k_zero_float<<<(8*FEAT + 255)/256, 256, 0, S1>>>(st, 8*FEAT);

    // ---- S1: layer0 self GEMMs ----
    gemm(S1, nbf_p, W(2), bsum0,     xp, nullptr, 0);        // protein self
    rec(E_PSELF, S1);
    gemm(S1, nbf_d, W(0), b1 + FEAT, xd, nullptr, 0);        // disease self

    // ---- S1: layer0 disease neigh + BN ----
    wait(S1, E_M1);
    gemm(S1, mbf1, W(1), nullptr, xd, st0d, 1);
    k_bnrelu<<<xgrid, 256, 0, S1>>>(xd, nbf_d, h16d, st0d, gam + 0*FEAT, bet + 0*FEAT, NN);
    rec(E_BND0, S1);

    // ---- S0: layer0 protein neigh + BN (aggs in-order on S0) ----
    wait(S0, E_PSELF);
    gemm(S0, mbf0, W(3), nullptr, xp, st0p, 1, mbf2, W(4), mbf3, W(5));
    k_bnrelu<<<xgrid, 256, 0, S0>>>(xp, nbf_p, h16p, st0p, gam + 1*FEAT, bet + 1*FEAT, NN);
    rec(E_BNP0, S0);

    // ---- layer1 aggregates ----
    // S0: m0' from h16d (E_BND0); mbf0 WAR vs pneigh_L0 in-order on S0
    wait(S0, E_BND0);
    k_aggregate<<<NN, 128, 0, S0>>>(mbf0, h16d, 0);
    k_aggregate<<<NN, 128, 0, S0>>>(mbf2, h16p, 2);
    k_aggregate<<<NN, 128, 0, S0>>>(mbf3, h16p, 3);

    // S1: m1' from h16p (E_BNP0); mbf1 WAR vs dneigh_L0 in-order on S1
    wait(S1, E_BNP0);
    k_aggregate<<<NN, 128, 0, S1>>>(mbf1, h16p, 1);

    // ---- S1: layer1 disease chain + projection ----
    gemm(S1, nbf_d, W(6), b2 + FEAT, xd, nullptr, 0);
    gemm(S1, mbf1,  W(7), nullptr,   xd, st1d, 1);
    k_bnrelu<<<xgrid, 256, 0, S1>>>(xd, nbf_d, nullptr, st1d, gam + 2*FEAT, bet + 2*FEAT, NN);
    gemm(S1, nbf_d, W(12), pbd, out, nullptr, 0);
    rec(E_S1, S1);

    // ---- S0: layer1 protein chain + projection ----
    gemm(S0, nbf_p, W(8), bsum1, xp, nullptr, 0);
    gemm(S0, mbf0,  W(9), nullptr, xp, st1p, 1, mbf2, W(10), mbf3, W(11));
    k_bnrelu<<<xgrid, 256, 0, S0>>>(xp, nbf_p, nullptr, st1p, gam + 3*FEAT, bet + 3*FEAT, NN);
    gemm(S0, nbf_p, W(13), pbp, out + (size_t)NN*FEAT, nullptr, 0);

    // join
    wait(S0, E_S1);
}